// round 1
// baseline (speedup 1.0000x reference)
#include <cuda_runtime.h>
#include <cuda_bf16.h>
#include <cstdint>

// Problem constants
#define CUR   512
#define FULL  1024
#define BS    4
#define DIMM  1024
#define NH    16
#define HD    64
#define PREV  (FULL - CUR)

// Scratch (device globals; no allocation allowed)
__device__ float g_KV[(size_t)FULL * BS * 2 * DIMM];          // (4096, 2048): [:,0:1024]=K, [:,1024:2048]=V
__device__ float g_Q [(size_t)CUR * BS * DIMM];               // (2048, 1024)
__device__ float g_R [(size_t)FULL * DIMM];                   // (1024, 1024) rows = rel pos k, cols = h*64+d
__device__ float g_S [(size_t)BS * NH * CUR * FULL];          // (bh, i, j) scores/probs
__device__ float g_AV[(size_t)CUR * BS * DIMM];               // (2048, 1024)

// ---------------------------------------------------------------------------
// Generic tiled GEMM: C(MxN) = A(MxK) * B(KxN) + bias(N)
// 64x64 tile, 16-deep k chunks, 256 threads, 4x4 per thread.
// ---------------------------------------------------------------------------
__global__ __launch_bounds__(256)
void gemm_bias_kernel(const float* __restrict__ A, const float* __restrict__ B,
                      const float* __restrict__ bias, float* __restrict__ C,
                      int M, int N, int K)
{
    __shared__ float As[16][64];   // As[k][m]
    __shared__ float Bs[16][64];   // Bs[k][n]

    const int tx = threadIdx.x;          // 0..15
    const int ty = threadIdx.y;          // 0..15
    const int tid = ty * 16 + tx;
    const int m0 = blockIdx.y * 64;
    const int n0 = blockIdx.x * 64;

    float acc[4][4] = {};

    for (int k0 = 0; k0 < K; k0 += 16) {
        #pragma unroll
        for (int t = tid; t < 64 * 16; t += 256) {
            int m = t >> 4, k = t & 15;
            As[k][m] = A[(size_t)(m0 + m) * K + k0 + k];
        }
        #pragma unroll
        for (int t = tid; t < 16 * 64; t += 256) {
            int k = t >> 6, n = t & 63;
            Bs[k][n] = B[(size_t)(k0 + k) * N + n0 + n];
        }
        __syncthreads();

        #pragma unroll
        for (int k = 0; k < 16; k++) {
            float a[4], b[4];
            #pragma unroll
            for (int x = 0; x < 4; x++) a[x] = As[k][ty * 4 + x];
            #pragma unroll
            for (int x = 0; x < 4; x++) b[x] = Bs[k][tx * 4 + x];
            #pragma unroll
            for (int ia = 0; ia < 4; ia++)
                #pragma unroll
                for (int jb = 0; jb < 4; jb++)
                    acc[ia][jb] += a[ia] * b[jb];
        }
        __syncthreads();
    }

    #pragma unroll
    for (int ia = 0; ia < 4; ia++) {
        int m = m0 + ty * 4 + ia;
        #pragma unroll
        for (int jb = 0; jb < 4; jb++) {
            int n = n0 + tx * 4 + jb;
            C[(size_t)m * N + n] = acc[ia][jb] + bias[n];
        }
    }
}

// ---------------------------------------------------------------------------
// Score kernel: S[bh, i, j] = scale * ( (Q[i,b,h]+u[h]) . K[j,b,h]
//                                     + (Q[i,b,h]+v[h]) . R[j-i+511, h] )
// Tile 64(i) x 64(j) per block; rel index within tile spans 127 R rows.
// Fully-masked tiles (j0 > i0+63+512) skipped; softmax writes zeros there.
// ---------------------------------------------------------------------------
__global__ __launch_bounds__(256)
void score_kernel(const float* __restrict__ Q, const float* __restrict__ KV,
                  const float* __restrict__ R, const float* __restrict__ u,
                  const float* __restrict__ v, float* __restrict__ S)
{
    const int bh = blockIdx.z;           // 0..63
    const int b = bh >> 4, h = bh & 15;
    const int i0 = blockIdx.y * 64;
    const int j0 = blockIdx.x * 64;
    if (j0 > i0 + 63 + PREV) return;     // entire tile masked

    __shared__ float Qu[16][64];
    __shared__ float Qv[16][64];
    __shared__ float Ks[16][64];
    __shared__ float Rs[16][128];

    const int tx = threadIdx.x, ty = threadIdx.y;
    const int tid = ty * 16 + tx;

    float acc[4][4] = {};
    const float* uh = u + h * HD;
    const float* vh = v + h * HD;
    const int kbase = j0 - i0 + (CUR - 1) - 63;  // global R row of local r=0

    for (int d0 = 0; d0 < HD; d0 += 16) {
        #pragma unroll
        for (int t = tid; t < 64 * 16; t += 256) {
            int ii = t >> 4, dd = t & 15;
            float q = Q[(size_t)((i0 + ii) * BS + b) * DIMM + h * HD + d0 + dd];
            Qu[dd][ii] = q + uh[d0 + dd];
            Qv[dd][ii] = q + vh[d0 + dd];
        }
        #pragma unroll
        for (int t = tid; t < 64 * 16; t += 256) {
            int jj = t >> 4, dd = t & 15;
            Ks[dd][jj] = KV[(size_t)((j0 + jj) * BS + b) * (2 * DIMM) + h * HD + d0 + dd];
        }
        #pragma unroll
        for (int t = tid; t < 128 * 16; t += 256) {
            int rr = t >> 4, dd = t & 15;
            int kg = kbase + rr;
            Rs[dd][rr] = (kg >= 0 && kg < FULL)
                       ? R[(size_t)kg * DIMM + h * HD + d0 + dd] : 0.f;
        }
        __syncthreads();

        const int rb = tx * 4 - ty * 4 + 63;
        #pragma unroll
        for (int dd = 0; dd < 16; dd++) {
            float a[4], av[4], bk[4];
            #pragma unroll
            for (int x = 0; x < 4; x++) {
                a[x]  = Qu[dd][ty * 4 + x];
                av[x] = Qv[dd][ty * 4 + x];
                bk[x] = Ks[dd][tx * 4 + x];
            }
            #pragma unroll
            for (int ia = 0; ia < 4; ia++)
                #pragma unroll
                for (int jc = 0; jc < 4; jc++)
                    acc[ia][jc] += a[ia] * bk[jc] + av[ia] * Rs[dd][rb + jc - ia];
        }
        __syncthreads();
    }

    const float scale = 0.125f;          // 1/sqrt(64)
    const size_t base = (size_t)bh * CUR * FULL;
    #pragma unroll
    for (int ia = 0; ia < 4; ia++) {
        int i = i0 + ty * 4 + ia;
        #pragma unroll
        for (int jc = 0; jc < 4; jc++) {
            int j = j0 + tx * 4 + jc;
            S[base + (size_t)i * FULL + j] = acc[ia][jc] * scale;
        }
    }
}

// ---------------------------------------------------------------------------
// Softmax over valid band j in [0, i+PREV]; zero the masked tail.
// One block per (i, bh) row.
// ---------------------------------------------------------------------------
__global__ __launch_bounds__(256)
void softmax_kernel(float* __restrict__ S)
{
    const int i = blockIdx.x;
    const int bh = blockIdx.y;
    float* row = S + ((size_t)bh * CUR + i) * FULL;
    const int L = i + PREV + 1;          // valid length
    const int tid = threadIdx.x;

    __shared__ float red[256];

    float m = -1e30f;
    for (int j = tid; j < L; j += 256) m = fmaxf(m, row[j]);
    red[tid] = m; __syncthreads();
    for (int s = 128; s > 0; s >>= 1) {
        if (tid < s) red[tid] = fmaxf(red[tid], red[tid + s]);
        __syncthreads();
    }
    m = red[0]; __syncthreads();

    float sum = 0.f;
    for (int j = tid; j < L; j += 256) sum += __expf(row[j] - m);
    red[tid] = sum; __syncthreads();
    for (int s = 128; s > 0; s >>= 1) {
        if (tid < s) red[tid] += red[tid + s];
        __syncthreads();
    }
    const float inv = 1.f / red[0];

    for (int j = tid; j < L; j += 256) row[j] = __expf(row[j] - m) * inv;
    for (int j = L + tid; j < FULL; j += 256) row[j] = 0.f;
}

// ---------------------------------------------------------------------------
// AV kernel: per (bh), AV[i, d] = sum_j S[bh,i,j] * V[j,b,h,d]
// 64(i) x 64(d) tile per block, band-limited j loop.
// ---------------------------------------------------------------------------
__global__ __launch_bounds__(256)
void av_kernel(const float* __restrict__ S, const float* __restrict__ KV,
               float* __restrict__ AV)
{
    const int bh = blockIdx.y;
    const int b = bh >> 4, h = bh & 15;
    const int i0 = blockIdx.x * 64;

    __shared__ float Ss[64][17];   // [i][k] with pad
    __shared__ float Vs[16][64];   // [k][d]

    const int tx = threadIdx.x, ty = threadIdx.y;
    const int tid = ty * 16 + tx;

    float acc[4][4] = {};
    const float* Sbase = S + ((size_t)bh * CUR + i0) * FULL;
    const int jmax = min(FULL, i0 + 64 + PREV);   // multiple of 16

    for (int j0 = 0; j0 < jmax; j0 += 16) {
        #pragma unroll
        for (int t = tid; t < 64 * 16; t += 256) {
            int ii = t >> 4, kk = t & 15;
            Ss[ii][kk] = Sbase[(size_t)ii * FULL + j0 + kk];
        }
        #pragma unroll
        for (int t = tid; t < 16 * 64; t += 256) {
            int kk = t >> 6, nn = t & 63;
            Vs[kk][nn] = KV[(size_t)((j0 + kk) * BS + b) * (2 * DIMM) + DIMM + h * HD + nn];
        }
        __syncthreads();

        #pragma unroll
        for (int kk = 0; kk < 16; kk++) {
            float a[4], bb[4];
            #pragma unroll
            for (int x = 0; x < 4; x++) a[x] = Ss[ty * 4 + x][kk];
            #pragma unroll
            for (int x = 0; x < 4; x++) bb[x] = Vs[kk][tx * 4 + x];
            #pragma unroll
            for (int ia = 0; ia < 4; ia++)
                #pragma unroll
                for (int nc = 0; nc < 4; nc++)
                    acc[ia][nc] += a[ia] * bb[nc];
        }
        __syncthreads();
    }

    #pragma unroll
    for (int ia = 0; ia < 4; ia++) {
        int i = i0 + ty * 4 + ia;
        #pragma unroll
        for (int nc = 0; nc < 4; nc++) {
            int n = tx * 4 + nc;
            AV[(size_t)(i * BS + b) * DIMM + h * HD + n] = acc[ia][nc];
        }
    }
}

// ---------------------------------------------------------------------------
// Launch
// ---------------------------------------------------------------------------
extern "C" void kernel_launch(void* const* d_in, const int* in_sizes, int n_in,
                              void* d_out, int out_size)
{
    const float* inputs  = (const float*)d_in[0];   // (512,4,1024)
    const float* pos_emb = (const float*)d_in[1];   // (1024,1,1024)
    const float* full_in = (const float*)d_in[2];   // (1024,4,1024)
    const float* u       = (const float*)d_in[3];   // (16,64)
    const float* v       = (const float*)d_in[4];   // (16,64)
    const float* W_kv    = (const float*)d_in[5];   // (1024,2048)
    const float* b_kv    = (const float*)d_in[6];   // (2048,)
    const float* W_q     = (const float*)d_in[7];   // (1024,1024)
    const float* b_q     = (const float*)d_in[8];   // (1024,)
    const float* W_pos   = (const float*)d_in[9];   // (1024,1024)
    const float* b_pos   = (const float*)d_in[10];  // (1024,)
    const float* W_proj  = (const float*)d_in[11];  // (1024,1024)
    const float* b_proj  = (const float*)d_in[12];  // (1024,)
    // d_in[13] = mask: recomputed analytically, not read.
    float* out = (float*)d_out;

    float *gKV, *gQ, *gR, *gS, *gAV;
    cudaGetSymbolAddress((void**)&gKV, g_KV);
    cudaGetSymbolAddress((void**)&gQ,  g_Q);
    cudaGetSymbolAddress((void**)&gR,  g_R);
    cudaGetSymbolAddress((void**)&gS,  g_S);
    cudaGetSymbolAddress((void**)&gAV, g_AV);

    dim3 thr(16, 16);

    // 1. KV = full_input @ W_kv + b_kv : (4096, 2048)
    gemm_bias_kernel<<<dim3(2 * DIMM / 64, FULL * BS / 64), thr>>>(
        full_in, W_kv, b_kv, gKV, FULL * BS, 2 * DIMM, DIMM);

    // 2. Q = inputs @ W_q + b_q : (2048, 1024)
    gemm_bias_kernel<<<dim3(DIMM / 64, CUR * BS / 64), thr>>>(
        inputs, W_q, b_q, gQ, CUR * BS, DIMM, DIMM);

    // 3. R = pos_embedding @ W_pos + b_pos : (1024, 1024)
    gemm_bias_kernel<<<dim3(DIMM / 64, FULL / 64), thr>>>(
        pos_emb, W_pos, b_pos, gR, FULL, DIMM, DIMM);

    // 4. Scores
    score_kernel<<<dim3(FULL / 64, CUR / 64, BS * NH), thr>>>(gQ, gKV, gR, u, v, gS);

    // 5. Softmax (band + zero tail)
    softmax_kernel<<<dim3(CUR, BS * NH), 256>>>(gS);

    // 6. AV
    av_kernel<<<dim3(CUR / 64, BS * NH), thr>>>(gS, gKV, gAV);

    // 7. out = AV @ W_proj + b_proj : (2048, 1024)
    gemm_bias_kernel<<<dim3(DIMM / 64, CUR * BS / 64), thr>>>(
        gAV, W_proj, b_proj, out, CUR * BS, DIMM, DIMM);
}

// round 2
// speedup vs baseline: 1.6372x; 1.6372x over previous
#include <cuda_runtime.h>
#include <cuda_bf16.h>
#include <cstdint>

// Problem constants
#define CUR   512
#define FULL  1024
#define BS    4
#define DIMM  1024
#define NH    16
#define HD    64
#define PREV  (FULL - CUR)

// Scratch (device globals; no allocation allowed)
__device__ float g_KV[(size_t)FULL * BS * 2 * DIMM];   // (4096, 2048): K | V
__device__ float g_Q [(size_t)CUR * BS * DIMM];        // (2048, 1024)
__device__ float g_R [(size_t)FULL * DIMM];            // (1024, 1024)
__device__ float g_C1[(size_t)BS * NH * CUR * FULL];   // content scores
__device__ float g_C2[(size_t)BS * NH * CUR * FULL];   // position scores (rel-k)
__device__ float g_S [(size_t)BS * NH * CUR * FULL];   // probs
__device__ float g_AV[(size_t)CUR * BS * DIMM];        // (2048, 1024)

// ---------------------------------------------------------------------------
// tf32 helpers (3xTF32 split for fp32-level accuracy on tensor cores)
// ---------------------------------------------------------------------------
__device__ __forceinline__ uint32_t f2tf32(float x) {
    uint32_t r; asm("cvt.rna.tf32.f32 %0, %1;" : "=r"(r) : "f"(x)); return r;
}
__device__ __forceinline__ void split_tf32(float x, float& hi, float& lo) {
    uint32_t h = f2tf32(x);
    hi = __uint_as_float(h);
    lo = __uint_as_float(f2tf32(x - hi));
}
__device__ __forceinline__ void mma8(float* d, const uint32_t* a, const uint32_t* b) {
    asm volatile(
        "mma.sync.aligned.m16n8k8.row.col.f32.tf32.tf32.f32 "
        "{%0,%1,%2,%3}, {%4,%5,%6,%7}, {%8,%9}, {%0,%1,%2,%3};"
        : "+f"(d[0]), "+f"(d[1]), "+f"(d[2]), "+f"(d[3])
        : "r"(a[0]), "r"(a[1]), "r"(a[2]), "r"(a[3]), "r"(b[0]), "r"(b[1]));
}

// ---------------------------------------------------------------------------
// Big GEMM: C(MxN) = A(MxK) * B(KxN) + bias(N). M,N mult of 128, K mult of 16.
// 128x128 block tile, Kc=16, 256 threads (8 warps, 2x4), warp tile 64x32.
// 3xTF32.
// ---------------------------------------------------------------------------
#define PADB 132
__global__ __launch_bounds__(256)
void gemm3t(const float* __restrict__ A, const float* __restrict__ B,
            const float* __restrict__ bias, float* __restrict__ C,
            int M, int N, int K)
{
    __shared__ float Ah[16][PADB], Al[16][PADB], Bh[16][PADB], Bl[16][PADB];

    const int tid = threadIdx.x;
    const int wid = tid >> 5, lane = tid & 31;
    const int wm = wid >> 2, wn = wid & 3;
    const int m0 = blockIdx.y * 128, n0 = blockIdx.x * 128;
    const int r = lane >> 2, c = lane & 3;

    float acc[4][4][4] = {};

    for (int k0 = 0; k0 < K; k0 += 16) {
        // A: 128x16, transpose to Ah/Al[k][m]
        {
            int m = tid >> 1;
            int kb = (tid & 1) * 8;
            #pragma unroll
            for (int q = 0; q < 2; q++) {
                float4 va = *(const float4*)&A[(size_t)(m0 + m) * K + k0 + kb + q * 4];
                float h, l;
                split_tf32(va.x, h, l); Ah[kb + q*4 + 0][m] = h; Al[kb + q*4 + 0][m] = l;
                split_tf32(va.y, h, l); Ah[kb + q*4 + 1][m] = h; Al[kb + q*4 + 1][m] = l;
                split_tf32(va.z, h, l); Ah[kb + q*4 + 2][m] = h; Al[kb + q*4 + 2][m] = l;
                split_tf32(va.w, h, l); Ah[kb + q*4 + 3][m] = h; Al[kb + q*4 + 3][m] = l;
            }
        }
        // B: 16x128, direct Bh/Bl[k][n]
        {
            int k = tid >> 4;
            int nb = (tid & 15) * 8;
            #pragma unroll
            for (int q = 0; q < 2; q++) {
                float4 vb = *(const float4*)&B[(size_t)(k0 + k) * N + n0 + nb + q * 4];
                float h, l;
                split_tf32(vb.x, h, l); Bh[k][nb + q*4 + 0] = h; Bl[k][nb + q*4 + 0] = l;
                split_tf32(vb.y, h, l); Bh[k][nb + q*4 + 1] = h; Bl[k][nb + q*4 + 1] = l;
                split_tf32(vb.z, h, l); Bh[k][nb + q*4 + 2] = h; Bl[k][nb + q*4 + 2] = l;
                split_tf32(vb.w, h, l); Bh[k][nb + q*4 + 3] = h; Bl[k][nb + q*4 + 3] = l;
            }
        }
        __syncthreads();

        #pragma unroll
        for (int s = 0; s < 2; s++) {
            const int ks = s * 8;
            uint32_t ah[4][4], al[4][4], bh[4][2], bl[4][2];
            #pragma unroll
            for (int f = 0; f < 4; f++) {
                int mm = wm * 64 + f * 16 + r;
                ah[f][0] = __float_as_uint(Ah[ks + c    ][mm    ]);
                ah[f][1] = __float_as_uint(Ah[ks + c    ][mm + 8]);
                ah[f][2] = __float_as_uint(Ah[ks + c + 4][mm    ]);
                ah[f][3] = __float_as_uint(Ah[ks + c + 4][mm + 8]);
                al[f][0] = __float_as_uint(Al[ks + c    ][mm    ]);
                al[f][1] = __float_as_uint(Al[ks + c    ][mm + 8]);
                al[f][2] = __float_as_uint(Al[ks + c + 4][mm    ]);
                al[f][3] = __float_as_uint(Al[ks + c + 4][mm + 8]);
            }
            #pragma unroll
            for (int g = 0; g < 4; g++) {
                int nn = wn * 32 + g * 8 + r;
                bh[g][0] = __float_as_uint(Bh[ks + c    ][nn]);
                bh[g][1] = __float_as_uint(Bh[ks + c + 4][nn]);
                bl[g][0] = __float_as_uint(Bl[ks + c    ][nn]);
                bl[g][1] = __float_as_uint(Bl[ks + c + 4][nn]);
            }
            #pragma unroll
            for (int f = 0; f < 4; f++)
                #pragma unroll
                for (int g = 0; g < 4; g++) {
                    mma8(acc[f][g], ah[f], bh[g]);
                    mma8(acc[f][g], ah[f], bl[g]);
                    mma8(acc[f][g], al[f], bh[g]);
                }
        }
        __syncthreads();
    }

    // Epilogue: +bias, float2 stores
    const int c2 = (lane & 3) * 2;
    #pragma unroll
    for (int f = 0; f < 4; f++) {
        int row0 = m0 + wm * 64 + f * 16 + r;
        #pragma unroll
        for (int g = 0; g < 4; g++) {
            int col = n0 + wn * 32 + g * 8 + c2;
            float2 b2 = *(const float2*)&bias[col];
            float2 s0 = { acc[f][g][0] + b2.x, acc[f][g][1] + b2.y };
            float2 s1 = { acc[f][g][2] + b2.x, acc[f][g][3] + b2.y };
            *(float2*)&C[(size_t)row0 * N + col]       = s0;
            *(float2*)&C[(size_t)(row0 + 8) * N + col] = s1;
        }
    }
}

// ---------------------------------------------------------------------------
// Batched score GEMM: Cout[bh,i,n] = sum_d (Q[i,b,h,d]+add[h,d]) * Brow(n)[d]
// MODE 0: Brow = K rows of KV (content).  MODE 1: Brow = R rows (position).
// Block: 64(i) x 64(n), K=64 in 4 chunks of 16. 128 thr, 4 warps (2x2),
// warp tile 32x32. 3xTF32. Band-masked tiles skipped.
// ---------------------------------------------------------------------------
template <int MODE>
__global__ __launch_bounds__(128)
void score3t(const float* __restrict__ Q, const float* __restrict__ Bsrc,
             const float* __restrict__ addv, float* __restrict__ Cout)
{
    const int bh = blockIdx.z;
    const int b = bh >> 4, h = bh & 15;
    const int i0 = blockIdx.y * 64, n0 = blockIdx.x * 64;
    if (MODE == 0) { if (n0 > i0 + 63 + PREV) return; }
    else           { if (n0 + i0 < 385) return; }

    __shared__ float Qh[16][68], Ql[16][68], Bh[16][68], Bl[16][68];

    const int tid = threadIdx.x;
    const int wid = tid >> 5, lane = tid & 31;
    const int wm = wid >> 1, wn = wid & 1;
    const int r = lane >> 2, c = lane & 3;

    const size_t brow_stride = (MODE == 0) ? (size_t)BS * 2 * DIMM : (size_t)DIMM;
    const float* bbase = Bsrc + ((MODE == 0) ? ((size_t)b * 2 * DIMM + h * HD)
                                             : ((size_t)h * HD));
    const float* addh = addv + h * HD;

    float acc[2][4][4] = {};

    for (int d0 = 0; d0 < HD; d0 += 16) {
        // Q tile: 64(i) x 16(d) -> Qh/Ql[d][i], with +u/v
        {
            int ii = tid >> 1;
            int db = (tid & 1) * 8;
            #pragma unroll
            for (int q = 0; q < 2; q++) {
                int d = db + q * 4;
                float4 va = *(const float4*)&Q[(size_t)((i0 + ii) * BS + b) * DIMM + h * HD + d0 + d];
                float4 ad = *(const float4*)&addh[d0 + d];
                float h_, l_;
                split_tf32(va.x + ad.x, h_, l_); Qh[d + 0][ii] = h_; Ql[d + 0][ii] = l_;
                split_tf32(va.y + ad.y, h_, l_); Qh[d + 1][ii] = h_; Ql[d + 1][ii] = l_;
                split_tf32(va.z + ad.z, h_, l_); Qh[d + 2][ii] = h_; Ql[d + 2][ii] = l_;
                split_tf32(va.w + ad.w, h_, l_); Qh[d + 3][ii] = h_; Ql[d + 3][ii] = l_;
            }
        }
        // B tile: 64(n) x 16(d) -> Bh/Bl[d][n]
        {
            int nn = tid >> 1;
            int db = (tid & 1) * 8;
            #pragma unroll
            for (int q = 0; q < 2; q++) {
                int d = db + q * 4;
                float4 vb = *(const float4*)&bbase[(size_t)(n0 + nn) * brow_stride + d0 + d];
                float h_, l_;
                split_tf32(vb.x, h_, l_); Bh[d + 0][nn] = h_; Bl[d + 0][nn] = l_;
                split_tf32(vb.y, h_, l_); Bh[d + 1][nn] = h_; Bl[d + 1][nn] = l_;
                split_tf32(vb.z, h_, l_); Bh[d + 2][nn] = h_; Bl[d + 2][nn] = l_;
                split_tf32(vb.w, h_, l_); Bh[d + 3][nn] = h_; Bl[d + 3][nn] = l_;
            }
        }
        __syncthreads();

        #pragma unroll
        for (int s = 0; s < 2; s++) {
            const int ks = s * 8;
            uint32_t ah[2][4], al[2][4], bhf[4][2], blf[4][2];
            #pragma unroll
            for (int f = 0; f < 2; f++) {
                int mm = wm * 32 + f * 16 + r;
                ah[f][0] = __float_as_uint(Qh[ks + c    ][mm    ]);
                ah[f][1] = __float_as_uint(Qh[ks + c    ][mm + 8]);
                ah[f][2] = __float_as_uint(Qh[ks + c + 4][mm    ]);
                ah[f][3] = __float_as_uint(Qh[ks + c + 4][mm + 8]);
                al[f][0] = __float_as_uint(Ql[ks + c    ][mm    ]);
                al[f][1] = __float_as_uint(Ql[ks + c    ][mm + 8]);
                al[f][2] = __float_as_uint(Ql[ks + c + 4][mm    ]);
                al[f][3] = __float_as_uint(Ql[ks + c + 4][mm + 8]);
            }
            #pragma unroll
            for (int g = 0; g < 4; g++) {
                int nn = wn * 32 + g * 8 + r;
                bhf[g][0] = __float_as_uint(Bh[ks + c    ][nn]);
                bhf[g][1] = __float_as_uint(Bh[ks + c + 4][nn]);
                blf[g][0] = __float_as_uint(Bl[ks + c    ][nn]);
                blf[g][1] = __float_as_uint(Bl[ks + c + 4][nn]);
            }
            #pragma unroll
            for (int f = 0; f < 2; f++)
                #pragma unroll
                for (int g = 0; g < 4; g++) {
                    mma8(acc[f][g], ah[f], bhf[g]);
                    mma8(acc[f][g], ah[f], blf[g]);
                    mma8(acc[f][g], al[f], bhf[g]);
                }
        }
        __syncthreads();
    }

    const int c2 = (lane & 3) * 2;
    const size_t obase = (size_t)bh * CUR * FULL;
    #pragma unroll
    for (int f = 0; f < 2; f++) {
        int row0 = i0 + wm * 32 + f * 16 + r;
        #pragma unroll
        for (int g = 0; g < 4; g++) {
            int col = n0 + wn * 32 + g * 8 + c2;
            float2 s0 = { acc[f][g][0], acc[f][g][1] };
            float2 s1 = { acc[f][g][2], acc[f][g][3] };
            *(float2*)&Cout[obase + (size_t)row0 * FULL + col]       = s0;
            *(float2*)&Cout[obase + (size_t)(row0 + 8) * FULL + col] = s1;
        }
    }
}

// ---------------------------------------------------------------------------
// Fused shift + mask + softmax. S[bh,i,j] = softmax_j( scale*(C1[i,j] +
// C2[i, j-i+511]) ) over j in [0, i+PREV]; zero tail.
// ---------------------------------------------------------------------------
__global__ __launch_bounds__(256)
void softmax_fused(const float* __restrict__ C1, const float* __restrict__ C2,
                   float* __restrict__ S)
{
    const int i = blockIdx.x;
    const int bh = blockIdx.y;
    const int L = i + PREV + 1;
    const int tid = threadIdx.x;
    const size_t rb = ((size_t)bh * CUR + i) * FULL;
    const float* r1 = C1 + rb;
    const float* r2 = C2 + rb + (CUR - 1 - i);
    float* row = S + rb;

    __shared__ float red[256];

    float m = -1e30f;
    for (int j = tid; j < L; j += 256) {
        float v = 0.125f * (r1[j] + r2[j]);
        row[j] = v;
        m = fmaxf(m, v);
    }
    red[tid] = m; __syncthreads();
    for (int s = 128; s > 0; s >>= 1) {
        if (tid < s) red[tid] = fmaxf(red[tid], red[tid + s]);
        __syncthreads();
    }
    m = red[0]; __syncthreads();

    float sum = 0.f;
    for (int j = tid; j < L; j += 256) sum += __expf(row[j] - m);
    red[tid] = sum; __syncthreads();
    for (int s = 128; s > 0; s >>= 1) {
        if (tid < s) red[tid] += red[tid + s];
        __syncthreads();
    }
    const float inv = 1.f / red[0];

    for (int j = tid; j < L; j += 256) row[j] = __expf(row[j] - m) * inv;
    for (int j = L + tid; j < FULL; j += 256) row[j] = 0.f;
}

// ---------------------------------------------------------------------------
// AV: per bh, AV[i,n] = sum_j S[i,j] * V[j,n]. 64x64 tile, Kc=32, band-limited.
// 128 thr, 4 warps (2x2), warp tile 32x32. 3xTF32.
// ---------------------------------------------------------------------------
__global__ __launch_bounds__(128)
void av3t(const float* __restrict__ S, const float* __restrict__ KV,
          float* __restrict__ AV)
{
    const int bh = blockIdx.y;
    const int b = bh >> 4, h = bh & 15;
    const int i0 = blockIdx.x * 64;

    __shared__ float Sh[32][68], Sl[32][68], Vh[32][68], Vl[32][68];

    const int tid = threadIdx.x;
    const int wid = tid >> 5, lane = tid & 31;
    const int wm = wid >> 1, wn = wid & 1;
    const int r = lane >> 2, c = lane & 3;

    const float* Sbase = S + ((size_t)bh * CUR + i0) * FULL;
    const float* Vbase = KV + (size_t)b * 2 * DIMM + DIMM + h * HD;
    const int jmax = min(FULL, i0 + 64 + PREV);

    float acc[2][4][4] = {};

    for (int j0 = 0; j0 < jmax; j0 += 32) {
        // S tile 64(i) x 32(j) -> Sh/Sl[j][i]
        {
            int ii = tid >> 1;
            int jb = (tid & 1) * 16;
            #pragma unroll
            for (int q = 0; q < 4; q++) {
                int jj = jb + q * 4;
                float4 vs = *(const float4*)&Sbase[(size_t)ii * FULL + j0 + jj];
                float h_, l_;
                split_tf32(vs.x, h_, l_); Sh[jj + 0][ii] = h_; Sl[jj + 0][ii] = l_;
                split_tf32(vs.y, h_, l_); Sh[jj + 1][ii] = h_; Sl[jj + 1][ii] = l_;
                split_tf32(vs.z, h_, l_); Sh[jj + 2][ii] = h_; Sl[jj + 2][ii] = l_;
                split_tf32(vs.w, h_, l_); Sh[jj + 3][ii] = h_; Sl[jj + 3][ii] = l_;
            }
        }
        // V tile 32(j) x 64(n) -> Vh/Vl[j][n]
        {
            int kk = tid >> 2;
            int nb = (tid & 3) * 16;
            #pragma unroll
            for (int q = 0; q < 4; q++) {
                int nn = nb + q * 4;
                float4 vv = *(const float4*)&Vbase[(size_t)(j0 + kk) * BS * 2 * DIMM + nn];
                float h_, l_;
                split_tf32(vv.x, h_, l_); Vh[kk][nn + 0] = h_; Vl[kk][nn + 0] = l_;
                split_tf32(vv.y, h_, l_); Vh[kk][nn + 1] = h_; Vl[kk][nn + 1] = l_;
                split_tf32(vv.z, h_, l_); Vh[kk][nn + 2] = h_; Vl[kk][nn + 2] = l_;
                split_tf32(vv.w, h_, l_); Vh[kk][nn + 3] = h_; Vl[kk][nn + 3] = l_;
            }
        }
        __syncthreads();

        #pragma unroll
        for (int s = 0; s < 4; s++) {
            const int ks = s * 8;
            uint32_t ah[2][4], al[2][4], bhf[4][2], blf[4][2];
            #pragma unroll
            for (int f = 0; f < 2; f++) {
                int mm = wm * 32 + f * 16 + r;
                ah[f][0] = __float_as_uint(Sh[ks + c    ][mm    ]);
                ah[f][1] = __float_as_uint(Sh[ks + c    ][mm + 8]);
                ah[f][2] = __float_as_uint(Sh[ks + c + 4][mm    ]);
                ah[f][3] = __float_as_uint(Sh[ks + c + 4][mm + 8]);
                al[f][0] = __float_as_uint(Sl[ks + c    ][mm    ]);
                al[f][1] = __float_as_uint(Sl[ks + c    ][mm + 8]);
                al[f][2] = __float_as_uint(Sl[ks + c + 4][mm    ]);
                al[f][3] = __float_as_uint(Sl[ks + c + 4][mm + 8]);
            }
            #pragma unroll
            for (int g = 0; g < 4; g++) {
                int nn = wn * 32 + g * 8 + r;
                bhf[g][0] = __float_as_uint(Vh[ks + c    ][nn]);
                bhf[g][1] = __float_as_uint(Vh[ks + c + 4][nn]);
                blf[g][0] = __float_as_uint(Vl[ks + c    ][nn]);
                blf[g][1] = __float_as_uint(Vl[ks + c + 4][nn]);
            }
            #pragma unroll
            for (int f = 0; f < 2; f++)
                #pragma unroll
                for (int g = 0; g < 4; g++) {
                    mma8(acc[f][g], ah[f], bhf[g]);
                    mma8(acc[f][g], ah[f], blf[g]);
                    mma8(acc[f][g], al[f], bhf[g]);
                }
        }
        __syncthreads();
    }

    const int c2 = (lane & 3) * 2;
    #pragma unroll
    for (int f = 0; f < 2; f++) {
        int row0 = i0 + wm * 32 + f * 16 + r;
        #pragma unroll
        for (int g = 0; g < 4; g++) {
            int col = wn * 32 + g * 8 + c2;
            float2 s0 = { acc[f][g][0], acc[f][g][1] };
            float2 s1 = { acc[f][g][2], acc[f][g][3] };
            *(float2*)&AV[(size_t)(row0 * BS + b) * DIMM + h * HD + col]       = s0;
            *(float2*)&AV[(size_t)((row0 + 8) * BS + b) * DIMM + h * HD + col] = s1;
        }
    }
}

// ---------------------------------------------------------------------------
// Launch
// ---------------------------------------------------------------------------
extern "C" void kernel_launch(void* const* d_in, const int* in_sizes, int n_in,
                              void* d_out, int out_size)
{
    const float* inputs  = (const float*)d_in[0];
    const float* pos_emb = (const float*)d_in[1];
    const float* full_in = (const float*)d_in[2];
    const float* u       = (const float*)d_in[3];
    const float* v       = (const float*)d_in[4];
    const float* W_kv    = (const float*)d_in[5];
    const float* b_kv    = (const float*)d_in[6];
    const float* W_q     = (const float*)d_in[7];
    const float* b_q     = (const float*)d_in[8];
    const float* W_pos   = (const float*)d_in[9];
    const float* b_pos   = (const float*)d_in[10];
    const float* W_proj  = (const float*)d_in[11];
    const float* b_proj  = (const float*)d_in[12];
    float* out = (float*)d_out;

    float *gKV, *gQ, *gR, *gC1, *gC2, *gS, *gAV;
    cudaGetSymbolAddress((void**)&gKV, g_KV);
    cudaGetSymbolAddress((void**)&gQ,  g_Q);
    cudaGetSymbolAddress((void**)&gR,  g_R);
    cudaGetSymbolAddress((void**)&gC1, g_C1);
    cudaGetSymbolAddress((void**)&gC2, g_C2);
    cudaGetSymbolAddress((void**)&gS,  g_S);
    cudaGetSymbolAddress((void**)&gAV, g_AV);

    // 1. KV = full_input @ W_kv + b_kv : (4096, 2048)
    gemm3t<<<dim3(2 * DIMM / 128, FULL * BS / 128), 256>>>(
        full_in, W_kv, b_kv, gKV, FULL * BS, 2 * DIMM, DIMM);

    // 2. Q = inputs @ W_q + b_q : (2048, 1024)
    gemm3t<<<dim3(DIMM / 128, CUR * BS / 128), 256>>>(
        inputs, W_q, b_q, gQ, CUR * BS, DIMM, DIMM);

    // 3. R = pos_embedding @ W_pos + b_pos : (1024, 1024)
    gemm3t<<<dim3(DIMM / 128, FULL / 128), 256>>>(
        pos_emb, W_pos, b_pos, gR, FULL, DIMM, DIMM);

    // 4a. Content scores: C1[bh,i,j] = (Q+u).K
    score3t<0><<<dim3(FULL / 64, CUR / 64, BS * NH), 128>>>(gQ, gKV, u, gC1);

    // 4b. Position scores: C2[bh,i,k] = (Q+v).R
    score3t<1><<<dim3(FULL / 64, CUR / 64, BS * NH), 128>>>(gQ, gR, v, gC2);

    // 5. Fused shift + mask + softmax
    softmax_fused<<<dim3(CUR, BS * NH), 256>>>(gC1, gC2, gS);

    // 6. AV
    av3t<<<dim3(CUR / 64, BS * NH), 128>>>(gS, gKV, gAV);

    // 7. out = AV @ W_proj + b_proj : (2048, 1024)
    gemm3t<<<dim3(DIMM / 128, CUR * BS / 128), 256>>>(
        gAV, W_proj, b_proj, out, CUR * BS, DIMM, DIMM);
}

// round 3
// speedup vs baseline: 2.6319x; 1.6075x over previous
#include <cuda_runtime.h>
#include <cuda_bf16.h>
#include <cstdint>

#define CUR   512
#define FULL  1024
#define BS    4
#define DIMM  1024
#define NH    16
#define HD    64
#define PREV  512

// Scratch
__device__ float g_KV[(size_t)FULL * BS * 2 * DIMM];   // (4096, 2048): K | V
__device__ float g_Q [(size_t)CUR * BS * DIMM];        // (2048, 1024)
__device__ float g_R [(size_t)FULL * DIMM];            // (1024, 1024)
__device__ float g_C2[(size_t)BS * NH * CUR * FULL];   // position scores (rel-k)
__device__ float g_AV[(size_t)CUR * BS * DIMM];        // (2048, 1024)

// ---------------------------------------------------------------------------
// helpers
// ---------------------------------------------------------------------------
__device__ __forceinline__ uint32_t smem_u32(const void* p) {
    return (uint32_t)__cvta_generic_to_shared(p);
}
__device__ __forceinline__ void ldsm4(uint32_t* r, uint32_t a) {
    asm volatile("ldmatrix.sync.aligned.m8n8.x4.shared.b16 {%0,%1,%2,%3}, [%4];"
        : "=r"(r[0]), "=r"(r[1]), "=r"(r[2]), "=r"(r[3]) : "r"(a));
}
__device__ __forceinline__ void ldsm4t(uint32_t* r, uint32_t a) {
    asm volatile("ldmatrix.sync.aligned.m8n8.x4.trans.shared.b16 {%0,%1,%2,%3}, [%4];"
        : "=r"(r[0]), "=r"(r[1]), "=r"(r[2]), "=r"(r[3]) : "r"(a));
}
__device__ __forceinline__ void mmabf(float* d, const uint32_t* a, const uint32_t* b) {
    asm volatile(
        "mma.sync.aligned.m16n8k16.row.col.f32.bf16.bf16.f32 "
        "{%0,%1,%2,%3},{%4,%5,%6,%7},{%8,%9},{%0,%1,%2,%3};"
        : "+f"(d[0]), "+f"(d[1]), "+f"(d[2]), "+f"(d[3])
        : "r"(a[0]), "r"(a[1]), "r"(a[2]), "r"(a[3]), "r"(b[0]), "r"(b[1]));
}
// Store two consecutive elements split into hi/lo bf16 tiles.
__device__ __forceinline__ void store_split(__nv_bfloat16* ph, __nv_bfloat16* pl,
                                            float x, float y) {
    __nv_bfloat16 hx = __float2bfloat16(x), hy = __float2bfloat16(y);
    __nv_bfloat162 H; H.x = hx; H.y = hy;
    __nv_bfloat162 L;
    L.x = __float2bfloat16(x - __bfloat162float(hx));
    L.y = __float2bfloat16(y - __bfloat162float(hy));
    *(__nv_bfloat162*)ph = H;
    *(__nv_bfloat162*)pl = L;
}
// Pack two floats into hi and lo bf16x2 registers.
__device__ __forceinline__ void split2(float x, float y, uint32_t& h, uint32_t& l) {
    __nv_bfloat16 hx = __float2bfloat16(x), hy = __float2bfloat16(y);
    __nv_bfloat162 H; H.x = hx; H.y = hy;
    __nv_bfloat162 L;
    L.x = __float2bfloat16(x - __bfloat162float(hx));
    L.y = __float2bfloat16(y - __bfloat162float(hy));
    h = *reinterpret_cast<uint32_t*>(&H);
    l = *reinterpret_cast<uint32_t*>(&L);
}

// ---------------------------------------------------------------------------
// Big GEMM: C(MxN) = A(MxK)*B(KxN) + bias. M,N mult of 128, K mult of 32.
// 128x128 tile, BK=32, 256 thr (8 warps, 4m x 2n), warp tile 32x64.
// bf16 hi/lo 3-term, ldmatrix.
// ---------------------------------------------------------------------------
__global__ __launch_bounds__(256)
void gemm_bf(const float* __restrict__ A, const float* __restrict__ B,
             const float* __restrict__ bias, float* __restrict__ C,
             int M, int N, int K)
{
    __shared__ __nv_bfloat16 Ah[128][40], Al[128][40];
    __shared__ __nv_bfloat16 Bh[32][136], Bl[32][136];

    const int tid = threadIdx.x, lane = tid & 31, wid = tid >> 5;
    const int wm = wid >> 1, wn = wid & 1;
    const int m0 = blockIdx.y * 128, n0 = blockIdx.x * 128;

    const int lam = tid >> 1, lak = (tid & 1) * 16;
    const int lbk = tid >> 3, lbn = (tid & 7) * 16;

    float acc[2][8][4] = {};

    for (int k0 = 0; k0 < K; k0 += 32) {
        #pragma unroll
        for (int q = 0; q < 4; q++) {
            float4 va = *(const float4*)&A[(size_t)(m0 + lam) * K + k0 + lak + q * 4];
            store_split(&Ah[lam][lak + q*4],     &Al[lam][lak + q*4],     va.x, va.y);
            store_split(&Ah[lam][lak + q*4 + 2], &Al[lam][lak + q*4 + 2], va.z, va.w);
        }
        #pragma unroll
        for (int q = 0; q < 4; q++) {
            float4 vb = *(const float4*)&B[(size_t)(k0 + lbk) * N + n0 + lbn + q * 4];
            store_split(&Bh[lbk][lbn + q*4],     &Bl[lbk][lbn + q*4],     vb.x, vb.y);
            store_split(&Bh[lbk][lbn + q*4 + 2], &Bl[lbk][lbn + q*4 + 2], vb.z, vb.w);
        }
        __syncthreads();

        #pragma unroll
        for (int s = 0; s < 2; s++) {
            const int ks = s * 16;
            uint32_t ahf[2][4], alf[2][4], bhf[8][2], blf[8][2];
            #pragma unroll
            for (int f = 0; f < 2; f++) {
                int row = wm * 32 + f * 16 + (lane & 15);
                int kc  = ks + ((lane & 16) >> 1);
                ldsm4(ahf[f], smem_u32(&Ah[row][kc]));
                ldsm4(alf[f], smem_u32(&Al[row][kc]));
            }
            #pragma unroll
            for (int g4 = 0; g4 < 4; g4++) {
                int krow = ks + (lane & 15);
                int nc   = wn * 64 + g4 * 16 + ((lane & 16) >> 1);
                uint32_t t[4];
                ldsm4t(t, smem_u32(&Bh[krow][nc]));
                bhf[2*g4][0] = t[0]; bhf[2*g4][1] = t[1];
                bhf[2*g4+1][0] = t[2]; bhf[2*g4+1][1] = t[3];
                ldsm4t(t, smem_u32(&Bl[krow][nc]));
                blf[2*g4][0] = t[0]; blf[2*g4][1] = t[1];
                blf[2*g4+1][0] = t[2]; blf[2*g4+1][1] = t[3];
            }
            #pragma unroll
            for (int f = 0; f < 2; f++)
                #pragma unroll
                for (int g = 0; g < 8; g++) {
                    mmabf(acc[f][g], ahf[f], bhf[g]);
                    mmabf(acc[f][g], ahf[f], blf[g]);
                    mmabf(acc[f][g], alf[f], bhf[g]);
                }
        }
        __syncthreads();
    }

    const int r = lane >> 2, c2 = (lane & 3) * 2;
    #pragma unroll
    for (int f = 0; f < 2; f++) {
        int row0 = m0 + wm * 32 + f * 16 + r;
        #pragma unroll
        for (int g = 0; g < 8; g++) {
            int col = n0 + wn * 64 + g * 8 + c2;
            float2 b2 = *(const float2*)&bias[col];
            float2 s0 = { acc[f][g][0] + b2.x, acc[f][g][1] + b2.y };
            float2 s1 = { acc[f][g][2] + b2.x, acc[f][g][3] + b2.y };
            *(float2*)&C[(size_t)row0 * N + col]       = s0;
            *(float2*)&C[(size_t)(row0 + 8) * N + col] = s1;
        }
    }
}

// ---------------------------------------------------------------------------
// Position scores: C2[bh,i,k] = (Q[i,b,h,:]+v[h,:]) . R[k, h*64:...]
// Block: 64(i) x 64(k), full d=64 in one stage. 128 thr, 4 warps (2x2).
// ---------------------------------------------------------------------------
__global__ __launch_bounds__(128)
void pos_scores(const float* __restrict__ Q, const float* __restrict__ R,
                const float* __restrict__ v, float* __restrict__ C2)
{
    const int bh = blockIdx.z, b = bh >> 4, h = bh & 15;
    const int i0 = blockIdx.y * 64, n0 = blockIdx.x * 64;
    if (n0 + i0 < 385) return;

    __shared__ __nv_bfloat16 Qh[64][72], Ql[64][72];
    __shared__ __nv_bfloat16 Rh[64][72], Rl[64][72];

    const int tid = threadIdx.x, lane = tid & 31, wid = tid >> 5;
    const int wm = wid >> 1, wn = wid & 1;

    const int ii = tid >> 1, dp = (tid & 1) * 32;
    {
        const float* qrow = Q + (size_t)((i0 + ii) * BS + b) * DIMM + h * HD;
        const float* vh = v + h * HD;
        #pragma unroll
        for (int q = 0; q < 8; q++) {
            float4 a = *(const float4*)&qrow[dp + q * 4];
            float4 ad = *(const float4*)&vh[dp + q * 4];
            store_split(&Qh[ii][dp + q*4],     &Ql[ii][dp + q*4],     a.x + ad.x, a.y + ad.y);
            store_split(&Qh[ii][dp + q*4 + 2], &Ql[ii][dp + q*4 + 2], a.z + ad.z, a.w + ad.w);
        }
        const float* rrow = R + (size_t)(n0 + ii) * DIMM + h * HD;
        #pragma unroll
        for (int q = 0; q < 8; q++) {
            float4 a = *(const float4*)&rrow[dp + q * 4];
            store_split(&Rh[ii][dp + q*4],     &Rl[ii][dp + q*4],     a.x, a.y);
            store_split(&Rh[ii][dp + q*4 + 2], &Rl[ii][dp + q*4 + 2], a.z, a.w);
        }
    }
    __syncthreads();

    float acc[2][4][4] = {};
    #pragma unroll
    for (int s = 0; s < 4; s++) {
        const int ks = s * 16;
        uint32_t ah[2][4], al[2][4], bh[4][2], bl[4][2];
        #pragma unroll
        for (int f = 0; f < 2; f++) {
            int row = wm * 32 + f * 16 + (lane & 15);
            int kc  = ks + ((lane & 16) >> 1);
            ldsm4(ah[f], smem_u32(&Qh[row][kc]));
            ldsm4(al[f], smem_u32(&Ql[row][kc]));
        }
        #pragma unroll
        for (int g4 = 0; g4 < 2; g4++) {
            int nrow = wn * 32 + g4 * 16 + (lane & 15);
            int kc   = ks + ((lane & 16) >> 1);
            uint32_t t[4];
            ldsm4(t, smem_u32(&Rh[nrow][kc]));   // non-trans: [n][k] storage
            bh[2*g4][0] = t[0]; bh[2*g4+1][0] = t[1];
            bh[2*g4][1] = t[2]; bh[2*g4+1][1] = t[3];
            ldsm4(t, smem_u32(&Rl[nrow][kc]));
            bl[2*g4][0] = t[0]; bl[2*g4+1][0] = t[1];
            bl[2*g4][1] = t[2]; bl[2*g4+1][1] = t[3];
        }
        #pragma unroll
        for (int f = 0; f < 2; f++)
            #pragma unroll
            for (int g = 0; g < 4; g++) {
                mmabf(acc[f][g], ah[f], bh[g]);
                mmabf(acc[f][g], ah[f], bl[g]);
                mmabf(acc[f][g], al[f], bh[g]);
            }
    }

    const int r = lane >> 2, c2 = (lane & 3) * 2;
    float* out = C2 + (size_t)bh * CUR * FULL;
    #pragma unroll
    for (int f = 0; f < 2; f++) {
        int row0 = i0 + wm * 32 + f * 16 + r;
        #pragma unroll
        for (int g = 0; g < 4; g++) {
            int col = n0 + wn * 32 + g * 8 + c2;
            float2 s0 = { acc[f][g][0], acc[f][g][1] };
            float2 s1 = { acc[f][g][2], acc[f][g][3] };
            *(float2*)&out[(size_t)row0 * FULL + col]       = s0;
            *(float2*)&out[(size_t)(row0 + 8) * FULL + col] = s1;
        }
    }
}

// ---------------------------------------------------------------------------
// Fused attention: content scores + shifted C2 + mask + online softmax + P@V.
// Block = (bh, i0-block of 64 rows). 128 thr, 4 warps; warp w owns 16 rows.
// ---------------------------------------------------------------------------
__global__ __launch_bounds__(128)
void attn_fused(const float* __restrict__ Q, const float* __restrict__ KV,
                const float* __restrict__ u, const float* __restrict__ C2,
                float* __restrict__ AV)
{
    const int bh = blockIdx.y, b = bh >> 4, h = bh & 15;
    const int i0 = blockIdx.x * 64;

    __shared__ __nv_bfloat16 S0h[64][72], S0l[64][72];  // Q then K
    __shared__ __nv_bfloat16 S1h[64][72], S1l[64][72];  // V

    const int tid = threadIdx.x, lane = tid & 31, w = tid >> 5;
    const int r = lane >> 2, cq = lane & 3;

    const int ii = tid >> 1, dp = (tid & 1) * 32;

    // Load Q + u into S0
    {
        const float* qrow = Q + (size_t)((i0 + ii) * BS + b) * DIMM + h * HD;
        const float* uh = u + h * HD;
        #pragma unroll
        for (int q = 0; q < 8; q++) {
            float4 a = *(const float4*)&qrow[dp + q * 4];
            float4 ad = *(const float4*)&uh[dp + q * 4];
            store_split(&S0h[ii][dp + q*4],     &S0l[ii][dp + q*4],     a.x + ad.x, a.y + ad.y);
            store_split(&S0h[ii][dp + q*4 + 2], &S0l[ii][dp + q*4 + 2], a.z + ad.z, a.w + ad.w);
        }
    }
    __syncthreads();

    // Preload Q A-frags (warp w: rows w*16..w*16+15)
    uint32_t qh[4][4], ql[4][4];
    #pragma unroll
    for (int s = 0; s < 4; s++) {
        int row = w * 16 + (lane & 15);
        int kc  = s * 16 + ((lane & 16) >> 1);
        ldsm4(qh[s], smem_u32(&S0h[row][kc]));
        ldsm4(ql[s], smem_u32(&S0l[row][kc]));
    }

    float oacc[8][4] = {};
    float m0 = -1e30f, m1 = -1e30f, l0 = 0.f, l1 = 0.f;

    const int irow0 = i0 + w * 16 + r;
    const float* c2row0 = C2 + ((size_t)bh * CUR + irow0) * FULL;
    const float* c2row1 = c2row0 + (size_t)8 * FULL;
    const float* kvbase = KV + (size_t)b * 2 * DIMM + h * HD;

    const int jtiles = i0 / 64 + 9;
    for (int jt = 0; jt < jtiles; jt++) {
        const int j0 = jt * 64;
        __syncthreads();
        // Load K tile -> S0, V tile -> S1
        {
            const float* krow = kvbase + (size_t)(j0 + ii) * BS * 2 * DIMM;
            const float* vrow = krow + DIMM;
            #pragma unroll
            for (int q = 0; q < 8; q++) {
                float4 a = *(const float4*)&krow[dp + q * 4];
                store_split(&S0h[ii][dp + q*4],     &S0l[ii][dp + q*4],     a.x, a.y);
                store_split(&S0h[ii][dp + q*4 + 2], &S0l[ii][dp + q*4 + 2], a.z, a.w);
                float4 vv = *(const float4*)&vrow[dp + q * 4];
                store_split(&S1h[ii][dp + q*4],     &S1l[ii][dp + q*4],     vv.x, vv.y);
                store_split(&S1h[ii][dp + q*4 + 2], &S1l[ii][dp + q*4 + 2], vv.z, vv.w);
            }
        }
        __syncthreads();

        // S = Qu . K
        float sacc[8][4] = {};
        #pragma unroll
        for (int s = 0; s < 4; s++) {
            const int ks = s * 16;
            uint32_t bhf[8][2], blf[8][2];
            #pragma unroll
            for (int g4 = 0; g4 < 4; g4++) {
                int nrow = g4 * 16 + (lane & 15);
                int kc   = ks + ((lane & 16) >> 1);
                uint32_t t[4];
                ldsm4(t, smem_u32(&S0h[nrow][kc]));
                bhf[2*g4][0] = t[0]; bhf[2*g4+1][0] = t[1];
                bhf[2*g4][1] = t[2]; bhf[2*g4+1][1] = t[3];
                ldsm4(t, smem_u32(&S0l[nrow][kc]));
                blf[2*g4][0] = t[0]; blf[2*g4+1][0] = t[1];
                blf[2*g4][1] = t[2]; blf[2*g4+1][1] = t[3];
            }
            #pragma unroll
            for (int g = 0; g < 8; g++) {
                mmabf(sacc[g], qh[s], bhf[g]);
                mmabf(sacc[g], qh[s], blf[g]);
                mmabf(sacc[g], ql[s], bhf[g]);
            }
        }

        // Add shifted C2, scale, mask
        const bool boundary = (j0 == i0 + PREV);
        #pragma unroll
        for (int g = 0; g < 8; g++) {
            int jg  = j0 + g * 8 + 2 * cq;
            int k00 = jg - irow0 + 511;
            int k10 = k00 - 8;
            if (!boundary) {
                sacc[g][0] = 0.125f * (sacc[g][0] + c2row0[k00]);
                sacc[g][1] = 0.125f * (sacc[g][1] + c2row0[k00 + 1]);
                sacc[g][2] = 0.125f * (sacc[g][2] + c2row1[k10]);
                sacc[g][3] = 0.125f * (sacc[g][3] + c2row1[k10 + 1]);
            } else {
                sacc[g][0] = (k00     <= 1023) ? 0.125f * (sacc[g][0] + c2row0[k00])     : -1e30f;
                sacc[g][1] = (k00 + 1 <= 1023) ? 0.125f * (sacc[g][1] + c2row0[k00 + 1]) : -1e30f;
                sacc[g][2] = (k10     <= 1023) ? 0.125f * (sacc[g][2] + c2row1[k10])     : -1e30f;
                sacc[g][3] = (k10 + 1 <= 1023) ? 0.125f * (sacc[g][3] + c2row1[k10 + 1]) : -1e30f;
            }
        }

        // Online softmax
        float mx0 = -1e30f, mx1 = -1e30f;
        #pragma unroll
        for (int g = 0; g < 8; g++) {
            mx0 = fmaxf(mx0, fmaxf(sacc[g][0], sacc[g][1]));
            mx1 = fmaxf(mx1, fmaxf(sacc[g][2], sacc[g][3]));
        }
        mx0 = fmaxf(mx0, __shfl_xor_sync(0xffffffffu, mx0, 1));
        mx0 = fmaxf(mx0, __shfl_xor_sync(0xffffffffu, mx0, 2));
        mx1 = fmaxf(mx1, __shfl_xor_sync(0xffffffffu, mx1, 1));
        mx1 = fmaxf(mx1, __shfl_xor_sync(0xffffffffu, mx1, 2));

        float mn0 = fmaxf(m0, mx0), mn1 = fmaxf(m1, mx1);
        float a0 = __expf(m0 - mn0), a1 = __expf(m1 - mn1);
        m0 = mn0; m1 = mn1;
        l0 *= a0; l1 *= a1;
        #pragma unroll
        for (int g = 0; g < 8; g++) {
            oacc[g][0] *= a0; oacc[g][1] *= a0;
            oacc[g][2] *= a1; oacc[g][3] *= a1;
        }

        float p[8][4];
        #pragma unroll
        for (int g = 0; g < 8; g++) {
            p[g][0] = __expf(sacc[g][0] - m0);
            p[g][1] = __expf(sacc[g][1] - m0);
            p[g][2] = __expf(sacc[g][2] - m1);
            p[g][3] = __expf(sacc[g][3] - m1);
            l0 += p[g][0] + p[g][1];
            l1 += p[g][2] + p[g][3];
        }

        // O += P @ V
        #pragma unroll
        for (int t4 = 0; t4 < 4; t4++) {
            uint32_t pah[4], pal[4];
            split2(p[2*t4][0],   p[2*t4][1],   pah[0], pal[0]);
            split2(p[2*t4][2],   p[2*t4][3],   pah[1], pal[1]);
            split2(p[2*t4+1][0], p[2*t4+1][1], pah[2], pal[2]);
            split2(p[2*t4+1][2], p[2*t4+1][3], pah[3], pal[3]);

            uint32_t vhf[8][2], vlf[8][2];
            #pragma unroll
            for (int g4 = 0; g4 < 4; g4++) {
                int krow = t4 * 16 + (lane & 15);
                int nc   = g4 * 16 + ((lane & 16) >> 1);
                uint32_t t[4];
                ldsm4t(t, smem_u32(&S1h[krow][nc]));
                vhf[2*g4][0] = t[0]; vhf[2*g4][1] = t[1];
                vhf[2*g4+1][0] = t[2]; vhf[2*g4+1][1] = t[3];
                ldsm4t(t, smem_u32(&S1l[krow][nc]));
                vlf[2*g4][0] = t[0]; vlf[2*g4][1] = t[1];
                vlf[2*g4+1][0] = t[2]; vlf[2*g4+1][1] = t[3];
            }
            #pragma unroll
            for (int g = 0; g < 8; g++) {
                mmabf(oacc[g], pah, vhf[g]);
                mmabf(oacc[g], pah, vlf[g]);
                mmabf(oacc[g], pal, vhf[g]);
            }
        }
    }

    // finalize
    l0 += __shfl_xor_sync(0xffffffffu, l0, 1);
    l0 += __shfl_xor_sync(0xffffffffu, l0, 2);
    l1 += __shfl_xor_sync(0xffffffffu, l1, 1);
    l1 += __shfl_xor_sync(0xffffffffu, l1, 2);
    const float inv0 = 1.f / l0, inv1 = 1.f / l1;

    float* out0 = AV + (size_t)(irow0 * BS + b) * DIMM + h * HD;
    float* out1 = AV + (size_t)((irow0 + 8) * BS + b) * DIMM + h * HD;
    #pragma unroll
    for (int g = 0; g < 8; g++) {
        int col = g * 8 + 2 * cq;
        float2 s0 = { oacc[g][0] * inv0, oacc[g][1] * inv0 };
        float2 s1 = { oacc[g][2] * inv1, oacc[g][3] * inv1 };
        *(float2*)&out0[col] = s0;
        *(float2*)&out1[col] = s1;
    }
}

// ---------------------------------------------------------------------------
// Launch
// ---------------------------------------------------------------------------
extern "C" void kernel_launch(void* const* d_in, const int* in_sizes, int n_in,
                              void* d_out, int out_size)
{
    const float* inputs  = (const float*)d_in[0];
    const float* pos_emb = (const float*)d_in[1];
    const float* full_in = (const float*)d_in[2];
    const float* u       = (const float*)d_in[3];
    const float* v       = (const float*)d_in[4];
    const float* W_kv    = (const float*)d_in[5];
    const float* b_kv    = (const float*)d_in[6];
    const float* W_q     = (const float*)d_in[7];
    const float* b_q     = (const float*)d_in[8];
    const float* W_pos   = (const float*)d_in[9];
    const float* b_pos   = (const float*)d_in[10];
    const float* W_proj  = (const float*)d_in[11];
    const float* b_proj  = (const float*)d_in[12];
    float* out = (float*)d_out;

    float *gKV, *gQ, *gR, *gC2, *gAV;
    cudaGetSymbolAddress((void**)&gKV, g_KV);
    cudaGetSymbolAddress((void**)&gQ,  g_Q);
    cudaGetSymbolAddress((void**)&gR,  g_R);
    cudaGetSymbolAddress((void**)&gC2, g_C2);
    cudaGetSymbolAddress((void**)&gAV, g_AV);

    // 1. KV = full_input @ W_kv + b_kv : (4096, 2048)
    gemm_bf<<<dim3(2 * DIMM / 128, FULL * BS / 128), 256>>>(
        full_in, W_kv, b_kv, gKV, FULL * BS, 2 * DIMM, DIMM);

    // 2. Q = inputs @ W_q + b_q : (2048, 1024)
    gemm_bf<<<dim3(DIMM / 128, CUR * BS / 128), 256>>>(
        inputs, W_q, b_q, gQ, CUR * BS, DIMM, DIMM);

    // 3. R = pos_embedding @ W_pos + b_pos : (1024, 1024)
    gemm_bf<<<dim3(DIMM / 128, FULL / 128), 256>>>(
        pos_emb, W_pos, b_pos, gR, FULL, DIMM, DIMM);

    // 4. Position scores C2[bh,i,k]
    pos_scores<<<dim3(FULL / 64, CUR / 64, BS * NH), 128>>>(gQ, gR, v, gC2);

    // 5. Fused content scores + shift + mask + softmax + AV
    attn_fused<<<dim3(CUR / 64, BS * NH), 128>>>(gQ, gKV, u, gC2, gAV);

    // 6. out = AV @ W_proj + b_proj : (2048, 1024)
    gemm_bf<<<dim3(DIMM / 128, CUR * BS / 128), 256>>>(
        gAV, W_proj, b_proj, out, CUR * BS, DIMM, DIMM);
}

// round 4
// speedup vs baseline: 3.5099x; 1.3336x over previous
#include <cuda_runtime.h>
#include <cuda_bf16.h>
#include <cstdint>

#define CUR   512
#define FULL  1024
#define BS    4
#define DIMM  1024
#define NH    16
#define HD    64
#define PREV  512

typedef __nv_bfloat16 bf;

// ---------------- scratch (bf16 hi/lo pairs + fp32 C2) ----------------
__device__ bf g_FIh[4194304], g_FIl[4194304];     // full_input
__device__ bf g_INh[2097152], g_INl[2097152];     // inputs
__device__ bf g_PEh[1048576], g_PEl[1048576];     // pos_embedding
__device__ bf g_Wkvh[2097152], g_Wkvl[2097152];
__device__ bf g_Wqh[1048576],  g_Wql[1048576];
__device__ bf g_Wph[1048576],  g_Wpl[1048576];
__device__ bf g_Wprh[1048576], g_Wprl[1048576];
__device__ bf g_KVh[8388608],  g_KVl[8388608];    // (4096,2048) K|V
__device__ bf g_Quh[2097152],  g_Qul[2097152];    // Q+u
__device__ bf g_Qvh[2097152],  g_Qvl[2097152];    // Q+v
__device__ bf g_Rh[1048576],   g_Rl[1048576];
__device__ bf g_AVh[2097152],  g_AVl[2097152];
__device__ float g_C2[(size_t)BS * NH * CUR * FULL];  // position scores fp32

// ---------------- helpers ----------------
__device__ __forceinline__ uint32_t smem_u32(const void* p) {
    return (uint32_t)__cvta_generic_to_shared(p);
}
__device__ __forceinline__ void ldsm4(uint32_t* r, uint32_t a) {
    asm volatile("ldmatrix.sync.aligned.m8n8.x4.shared.b16 {%0,%1,%2,%3}, [%4];"
        : "=r"(r[0]), "=r"(r[1]), "=r"(r[2]), "=r"(r[3]) : "r"(a));
}
__device__ __forceinline__ void ldsm4t(uint32_t* r, uint32_t a) {
    asm volatile("ldmatrix.sync.aligned.m8n8.x4.trans.shared.b16 {%0,%1,%2,%3}, [%4];"
        : "=r"(r[0]), "=r"(r[1]), "=r"(r[2]), "=r"(r[3]) : "r"(a));
}
__device__ __forceinline__ void mmabf(float* d, const uint32_t* a, const uint32_t* b) {
    asm volatile(
        "mma.sync.aligned.m16n8k16.row.col.f32.bf16.bf16.f32 "
        "{%0,%1,%2,%3},{%4,%5,%6,%7},{%8,%9},{%0,%1,%2,%3};"
        : "+f"(d[0]), "+f"(d[1]), "+f"(d[2]), "+f"(d[3])
        : "r"(a[0]), "r"(a[1]), "r"(a[2]), "r"(a[3]), "r"(b[0]), "r"(b[1]));
}
__device__ __forceinline__ void store_split(bf* ph, bf* pl, float x, float y) {
    bf hx = __float2bfloat16(x), hy = __float2bfloat16(y);
    __nv_bfloat162 H; H.x = hx; H.y = hy;
    __nv_bfloat162 L;
    L.x = __float2bfloat16(x - __bfloat162float(hx));
    L.y = __float2bfloat16(y - __bfloat162float(hy));
    *(__nv_bfloat162*)ph = H;
    *(__nv_bfloat162*)pl = L;
}
__device__ __forceinline__ void split2(float x, float y, uint32_t& h, uint32_t& l) {
    bf hx = __float2bfloat16(x), hy = __float2bfloat16(y);
    __nv_bfloat162 H; H.x = hx; H.y = hy;
    __nv_bfloat162 L;
    L.x = __float2bfloat16(x - __bfloat162float(hx));
    L.y = __float2bfloat16(y - __bfloat162float(hy));
    h = *reinterpret_cast<uint32_t*>(&H);
    l = *reinterpret_cast<uint32_t*>(&L);
}

// ---------------- fp32 -> bf16 hi/lo converter ----------------
__global__ __launch_bounds__(256)
void cvt_split(const float* __restrict__ x, bf* __restrict__ h,
               bf* __restrict__ l, int n)
{
    int i = (blockIdx.x * 256 + threadIdx.x) * 4;
    if (i < n) {
        float4 v = *(const float4*)&x[i];
        store_split(&h[i],     &l[i],     v.x, v.y);
        store_split(&h[i + 2], &l[i + 2], v.z, v.w);
    }
}

// ---------------------------------------------------------------------------
// bf16-native GEMM: C(MxN) = A*B (+bias). 128x128 tile, BK=32, 256 thr,
// 8 warps (4m x 2n), warp tile 32x64, 3-term hi/lo, register-prefetch pipeline.
// MODE 0: fp32 out + bias. MODE 1: split bf16 out + bias.
// MODE 2: dual split bf16 out, biases (bias+uvec) and (bias+vvec).
// ---------------------------------------------------------------------------
template <int MODE>
__global__ __launch_bounds__(256)
void gemm_bb(const bf* __restrict__ Ah, const bf* __restrict__ Al,
             const bf* __restrict__ Bh, const bf* __restrict__ Bl,
             const float* __restrict__ bias, const float* __restrict__ uvec,
             const float* __restrict__ vvec,
             float* __restrict__ Cf,
             bf* __restrict__ Xh, bf* __restrict__ Xl,
             bf* __restrict__ Yh, bf* __restrict__ Yl,
             int M, int N, int K)
{
    __shared__ bf sAh[128][40], sAl[128][40];
    __shared__ bf sBh[32][136], sBl[32][136];

    const int tid = threadIdx.x, lane = tid & 31, wid = tid >> 5;
    const int wm = wid >> 1, wn = wid & 1;
    const int m0 = blockIdx.y * 128, n0 = blockIdx.x * 128;

    const int lam = tid >> 1, lak = (tid & 1) * 16;
    const int lbk = tid >> 3, lbn = (tid & 7) * 16;

    const bf* pAh = Ah + (size_t)(m0 + lam) * K + lak;
    const bf* pAl = Al + (size_t)(m0 + lam) * K + lak;
    const bf* pBh = Bh + (size_t)lbk * N + n0 + lbn;
    const bf* pBl = Bl + (size_t)lbk * N + n0 + lbn;

    uint4 ra[4], rb[4];
    ra[0] = *(const uint4*)&pAh[0]; ra[1] = *(const uint4*)&pAh[8];
    ra[2] = *(const uint4*)&pAl[0]; ra[3] = *(const uint4*)&pAl[8];
    rb[0] = *(const uint4*)&pBh[0]; rb[1] = *(const uint4*)&pBh[8];
    rb[2] = *(const uint4*)&pBl[0]; rb[3] = *(const uint4*)&pBl[8];

    float acc[2][8][4] = {};

    for (int k0 = 0; k0 < K; k0 += 32) {
        *(uint4*)&sAh[lam][lak]     = ra[0];
        *(uint4*)&sAh[lam][lak + 8] = ra[1];
        *(uint4*)&sAl[lam][lak]     = ra[2];
        *(uint4*)&sAl[lam][lak + 8] = ra[3];
        *(uint4*)&sBh[lbk][lbn]     = rb[0];
        *(uint4*)&sBh[lbk][lbn + 8] = rb[1];
        *(uint4*)&sBl[lbk][lbn]     = rb[2];
        *(uint4*)&sBl[lbk][lbn + 8] = rb[3];
        __syncthreads();

        if (k0 + 32 < K) {
            const bf* qAh = pAh + k0 + 32;
            const bf* qAl = pAl + k0 + 32;
            const bf* qBh = pBh + (size_t)(k0 + 32) * N;
            const bf* qBl = pBl + (size_t)(k0 + 32) * N;
            ra[0] = *(const uint4*)&qAh[0]; ra[1] = *(const uint4*)&qAh[8];
            ra[2] = *(const uint4*)&qAl[0]; ra[3] = *(const uint4*)&qAl[8];
            rb[0] = *(const uint4*)&qBh[0]; rb[1] = *(const uint4*)&qBh[8];
            rb[2] = *(const uint4*)&qBl[0]; rb[3] = *(const uint4*)&qBl[8];
        }

        #pragma unroll
        for (int s = 0; s < 2; s++) {
            const int ks = s * 16;
            uint32_t ahf[2][4], alf[2][4], bhf[8][2], blf[8][2];
            #pragma unroll
            for (int f = 0; f < 2; f++) {
                int row = wm * 32 + f * 16 + (lane & 15);
                int kc  = ks + ((lane & 16) >> 1);
                ldsm4(ahf[f], smem_u32(&sAh[row][kc]));
                ldsm4(alf[f], smem_u32(&sAl[row][kc]));
            }
            #pragma unroll
            for (int g4 = 0; g4 < 4; g4++) {
                int krow = ks + (lane & 15);
                int nc   = wn * 64 + g4 * 16 + ((lane & 16) >> 1);
                uint32_t t[4];
                ldsm4t(t, smem_u32(&sBh[krow][nc]));
                bhf[2*g4][0] = t[0]; bhf[2*g4][1] = t[1];
                bhf[2*g4+1][0] = t[2]; bhf[2*g4+1][1] = t[3];
                ldsm4t(t, smem_u32(&sBl[krow][nc]));
                blf[2*g4][0] = t[0]; blf[2*g4][1] = t[1];
                blf[2*g4+1][0] = t[2]; blf[2*g4+1][1] = t[3];
            }
            #pragma unroll
            for (int f = 0; f < 2; f++)
                #pragma unroll
                for (int g = 0; g < 8; g++) {
                    mmabf(acc[f][g], ahf[f], bhf[g]);
                    mmabf(acc[f][g], ahf[f], blf[g]);
                    mmabf(acc[f][g], alf[f], bhf[g]);
                }
        }
        __syncthreads();
    }

    const int r = lane >> 2, c2 = (lane & 3) * 2;
    #pragma unroll
    for (int f = 0; f < 2; f++) {
        int row0 = m0 + wm * 32 + f * 16 + r;
        #pragma unroll
        for (int g = 0; g < 8; g++) {
            int col = n0 + wn * 64 + g * 8 + c2;
            float2 b2 = *(const float2*)&bias[col];
            float v00 = acc[f][g][0] + b2.x, v01 = acc[f][g][1] + b2.y;
            float v10 = acc[f][g][2] + b2.x, v11 = acc[f][g][3] + b2.y;
            size_t i0o = (size_t)row0 * N + col;
            size_t i1o = (size_t)(row0 + 8) * N + col;
            if (MODE == 0) {
                *(float2*)&Cf[i0o] = make_float2(v00, v01);
                *(float2*)&Cf[i1o] = make_float2(v10, v11);
            } else if (MODE == 1) {
                store_split(&Xh[i0o], &Xl[i0o], v00, v01);
                store_split(&Xh[i1o], &Xl[i1o], v10, v11);
            } else {
                float2 uu = *(const float2*)&uvec[col];
                float2 vv = *(const float2*)&vvec[col];
                store_split(&Xh[i0o], &Xl[i0o], v00 + uu.x, v01 + uu.y);
                store_split(&Xh[i1o], &Xl[i1o], v10 + uu.x, v11 + uu.y);
                store_split(&Yh[i0o], &Yl[i0o], v00 + vv.x, v01 + vv.y);
                store_split(&Yh[i1o], &Yl[i1o], v10 + vv.x, v11 + vv.y);
            }
        }
    }
}

// ---------------------------------------------------------------------------
// Position scores: C2[bh,i,k] = Qv[i,b,h,:] . R[k, h*64:...]. 64x64 tile,
// 128 thr, 4 warps (2x2). bf16-native loads.
// ---------------------------------------------------------------------------
__global__ __launch_bounds__(128)
void pos_scores_bb(const bf* __restrict__ Qvh, const bf* __restrict__ Qvl,
                   const bf* __restrict__ Rh, const bf* __restrict__ Rl,
                   float* __restrict__ C2)
{
    const int bh = blockIdx.z, b = bh >> 4, h = bh & 15;
    const int i0 = blockIdx.y * 64, n0 = blockIdx.x * 64;
    if (n0 + i0 < 385) return;

    __shared__ bf sQh[64][72], sQl[64][72], sRh[64][72], sRl[64][72];

    const int tid = threadIdx.x, lane = tid & 31, wid = tid >> 5;
    const int wm = wid >> 1, wn = wid & 1;

    {
        const int row = tid >> 1, cb = (tid & 1) * 32;
        const size_t qoff = (size_t)((i0 + row) * BS + b) * DIMM + h * HD + cb;
        const size_t roff = (size_t)(n0 + row) * DIMM + h * HD + cb;
        #pragma unroll
        for (int q = 0; q < 4; q++) {
            *(uint4*)&sQh[row][cb + q * 8] = *(const uint4*)&Qvh[qoff + q * 8];
            *(uint4*)&sQl[row][cb + q * 8] = *(const uint4*)&Qvl[qoff + q * 8];
            *(uint4*)&sRh[row][cb + q * 8] = *(const uint4*)&Rh[roff + q * 8];
            *(uint4*)&sRl[row][cb + q * 8] = *(const uint4*)&Rl[roff + q * 8];
        }
    }
    __syncthreads();

    float acc[2][4][4] = {};
    #pragma unroll
    for (int s = 0; s < 4; s++) {
        const int ks = s * 16;
        uint32_t ah[2][4], al[2][4], bh2[4][2], bl2[4][2];
        #pragma unroll
        for (int f = 0; f < 2; f++) {
            int row = wm * 32 + f * 16 + (lane & 15);
            int kc  = ks + ((lane & 16) >> 1);
            ldsm4(ah[f], smem_u32(&sQh[row][kc]));
            ldsm4(al[f], smem_u32(&sQl[row][kc]));
        }
        #pragma unroll
        for (int g4 = 0; g4 < 2; g4++) {
            int nrow = wn * 32 + g4 * 16 + (lane & 15);
            int kc   = ks + ((lane & 16) >> 1);
            uint32_t t[4];
            ldsm4(t, smem_u32(&sRh[nrow][kc]));
            bh2[2*g4][0] = t[0]; bh2[2*g4+1][0] = t[1];
            bh2[2*g4][1] = t[2]; bh2[2*g4+1][1] = t[3];
            ldsm4(t, smem_u32(&sRl[nrow][kc]));
            bl2[2*g4][0] = t[0]; bl2[2*g4+1][0] = t[1];
            bl2[2*g4][1] = t[2]; bl2[2*g4+1][1] = t[3];
        }
        #pragma unroll
        for (int f = 0; f < 2; f++)
            #pragma unroll
            for (int g = 0; g < 4; g++) {
                mmabf(acc[f][g], ah[f], bh2[g]);
                mmabf(acc[f][g], ah[f], bl2[g]);
                mmabf(acc[f][g], al[f], bh2[g]);
            }
    }

    const int r = lane >> 2, c2 = (lane & 3) * 2;
    float* out = C2 + (size_t)bh * CUR * FULL;
    #pragma unroll
    for (int f = 0; f < 2; f++) {
        int row0 = i0 + wm * 32 + f * 16 + r;
        #pragma unroll
        for (int g = 0; g < 4; g++) {
            int col = n0 + wn * 32 + g * 8 + c2;
            *(float2*)&out[(size_t)row0 * FULL + col]       = make_float2(acc[f][g][0], acc[f][g][1]);
            *(float2*)&out[(size_t)(row0 + 8) * FULL + col] = make_float2(acc[f][g][2], acc[f][g][3]);
        }
    }
}

// ---------------------------------------------------------------------------
// Fused attention, bf16-native. 64 rows / block, 128 thr, 4 warps.
// ---------------------------------------------------------------------------
__global__ __launch_bounds__(128)
void attn_fused_bb(const bf* __restrict__ Quh, const bf* __restrict__ Qul,
                   const bf* __restrict__ KVh, const bf* __restrict__ KVl,
                   const float* __restrict__ C2,
                   bf* __restrict__ AVh, bf* __restrict__ AVl)
{
    const int bh = blockIdx.y, b = bh >> 4, h = bh & 15;
    const int i0 = blockIdx.x * 64;

    __shared__ bf S0h[64][72], S0l[64][72];  // Q then K
    __shared__ bf S1h[64][72], S1l[64][72];  // V

    const int tid = threadIdx.x, lane = tid & 31, w = tid >> 5;
    const int r = lane >> 2, cq = lane & 3;
    const int ii = tid >> 1, cb = (tid & 1) * 32;

    {
        const size_t qoff = (size_t)((i0 + ii) * BS + b) * DIMM + h * HD + cb;
        #pragma unroll
        for (int q = 0; q < 4; q++) {
            *(uint4*)&S0h[ii][cb + q * 8] = *(const uint4*)&Quh[qoff + q * 8];
            *(uint4*)&S0l[ii][cb + q * 8] = *(const uint4*)&Qul[qoff + q * 8];
        }
    }
    __syncthreads();

    uint32_t qh[4][4], ql[4][4];
    #pragma unroll
    for (int s = 0; s < 4; s++) {
        int row = w * 16 + (lane & 15);
        int kc  = s * 16 + ((lane & 16) >> 1);
        ldsm4(qh[s], smem_u32(&S0h[row][kc]));
        ldsm4(ql[s], smem_u32(&S0l[row][kc]));
    }

    float oacc[8][4] = {};
    float m0 = -1e30f, m1 = -1e30f, l0 = 0.f, l1 = 0.f;

    const int irow0 = i0 + w * 16 + r;
    const float* c2row0 = C2 + ((size_t)bh * CUR + irow0) * FULL;
    const float* c2row1 = c2row0 + (size_t)8 * FULL;

    const int jtiles = i0 / 64 + 9;
    for (int jt = 0; jt < jtiles; jt++) {
        const int j0 = jt * 64;
        __syncthreads();
        {
            const size_t koff = (size_t)((j0 + ii) * BS + b) * (2 * DIMM) + h * HD + cb;
            #pragma unroll
            for (int q = 0; q < 4; q++) {
                *(uint4*)&S0h[ii][cb + q * 8] = *(const uint4*)&KVh[koff + q * 8];
                *(uint4*)&S0l[ii][cb + q * 8] = *(const uint4*)&KVl[koff + q * 8];
                *(uint4*)&S1h[ii][cb + q * 8] = *(const uint4*)&KVh[koff + DIMM + q * 8];
                *(uint4*)&S1l[ii][cb + q * 8] = *(const uint4*)&KVl[koff + DIMM + q * 8];
            }
        }
        __syncthreads();

        float sacc[8][4] = {};
        #pragma unroll
        for (int s = 0; s < 4; s++) {
            const int ks = s * 16;
            uint32_t bhf[8][2], blf[8][2];
            #pragma unroll
            for (int g4 = 0; g4 < 4; g4++) {
                int nrow = g4 * 16 + (lane & 15);
                int kc   = ks + ((lane & 16) >> 1);
                uint32_t t[4];
                ldsm4(t, smem_u32(&S0h[nrow][kc]));
                bhf[2*g4][0] = t[0]; bhf[2*g4+1][0] = t[1];
                bhf[2*g4][1] = t[2]; bhf[2*g4+1][1] = t[3];
                ldsm4(t, smem_u32(&S0l[nrow][kc]));
                blf[2*g4][0] = t[0]; blf[2*g4+1][0] = t[1];
                blf[2*g4][1] = t[2]; blf[2*g4+1][1] = t[3];
            }
            #pragma unroll
            for (int g = 0; g < 8; g++) {
                mmabf(sacc[g], qh[s], bhf[g]);
                mmabf(sacc[g], qh[s], blf[g]);
                mmabf(sacc[g], ql[s], bhf[g]);
            }
        }

        const bool boundary = (j0 == i0 + PREV);
        #pragma unroll
        for (int g = 0; g < 8; g++) {
            int jg  = j0 + g * 8 + 2 * cq;
            int k00 = jg - irow0 + 511;
            int k10 = k00 - 8;
            if (!boundary) {
                sacc[g][0] = 0.125f * (sacc[g][0] + c2row0[k00]);
                sacc[g][1] = 0.125f * (sacc[g][1] + c2row0[k00 + 1]);
                sacc[g][2] = 0.125f * (sacc[g][2] + c2row1[k10]);
                sacc[g][3] = 0.125f * (sacc[g][3] + c2row1[k10 + 1]);
            } else {
                sacc[g][0] = (k00     <= 1023) ? 0.125f * (sacc[g][0] + c2row0[k00])     : -1e30f;
                sacc[g][1] = (k00 + 1 <= 1023) ? 0.125f * (sacc[g][1] + c2row0[k00 + 1]) : -1e30f;
                sacc[g][2] = (k10     <= 1023) ? 0.125f * (sacc[g][2] + c2row1[k10])     : -1e30f;
                sacc[g][3] = (k10 + 1 <= 1023) ? 0.125f * (sacc[g][3] + c2row1[k10 + 1]) : -1e30f;
            }
        }

        float mx0 = -1e30f, mx1 = -1e30f;
        #pragma unroll
        for (int g = 0; g < 8; g++) {
            mx0 = fmaxf(mx0, fmaxf(sacc[g][0], sacc[g][1]));
            mx1 = fmaxf(mx1, fmaxf(sacc[g][2], sacc[g][3]));
        }
        mx0 = fmaxf(mx0, __shfl_xor_sync(0xffffffffu, mx0, 1));
        mx0 = fmaxf(mx0, __shfl_xor_sync(0xffffffffu, mx0, 2));
        mx1 = fmaxf(mx1, __shfl_xor_sync(0xffffffffu, mx1, 1));
        mx1 = fmaxf(mx1, __shfl_xor_sync(0xffffffffu, mx1, 2));

        float mn0 = fmaxf(m0, mx0), mn1 = fmaxf(m1, mx1);
        float a0 = __expf(m0 - mn0), a1 = __expf(m1 - mn1);
        m0 = mn0; m1 = mn1;
        l0 *= a0; l1 *= a1;
        #pragma unroll
        for (int g = 0; g < 8; g++) {
            oacc[g][0] *= a0; oacc[g][1] *= a0;
            oacc[g][2] *= a1; oacc[g][3] *= a1;
        }

        float p[8][4];
        #pragma unroll
        for (int g = 0; g < 8; g++) {
            p[g][0] = __expf(sacc[g][0] - m0);
            p[g][1] = __expf(sacc[g][1] - m0);
            p[g][2] = __expf(sacc[g][2] - m1);
            p[g][3] = __expf(sacc[g][3] - m1);
            l0 += p[g][0] + p[g][1];
            l1 += p[g][2] + p[g][3];
        }

        #pragma unroll
        for (int t4 = 0; t4 < 4; t4++) {
            uint32_t pah[4], pal[4];
            split2(p[2*t4][0],   p[2*t4][1],   pah[0], pal[0]);
            split2(p[2*t4][2],   p[2*t4][3],   pah[1], pal[1]);
            split2(p[2*t4+1][0], p[2*t4+1][1], pah[2], pal[2]);
            split2(p[2*t4+1][2], p[2*t4+1][3], pah[3], pal[3]);

            uint32_t vhf[8][2], vlf[8][2];
            #pragma unroll
            for (int g4 = 0; g4 < 4; g4++) {
                int krow = t4 * 16 + (lane & 15);
                int nc   = g4 * 16 + ((lane & 16) >> 1);
                uint32_t t[4];
                ldsm4t(t, smem_u32(&S1h[krow][nc]));
                vhf[2*g4][0] = t[0]; vhf[2*g4][1] = t[1];
                vhf[2*g4+1][0] = t[2]; vhf[2*g4+1][1] = t[3];
                ldsm4t(t, smem_u32(&S1l[krow][nc]));
                vlf[2*g4][0] = t[0]; vlf[2*g4][1] = t[1];
                vlf[2*g4+1][0] = t[2]; vlf[2*g4+1][1] = t[3];
            }
            #pragma unroll
            for (int g = 0; g < 8; g++) {
                mmabf(oacc[g], pah, vhf[g]);
                mmabf(oacc[g], pah, vlf[g]);
                mmabf(oacc[g], pal, vhf[g]);
            }
        }
    }

    l0 += __shfl_xor_sync(0xffffffffu, l0, 1);
    l0 += __shfl_xor_sync(0xffffffffu, l0, 2);
    l1 += __shfl_xor_sync(0xffffffffu, l1, 1);
    l1 += __shfl_xor_sync(0xffffffffu, l1, 2);
    const float inv0 = 1.f / l0, inv1 = 1.f / l1;

    const size_t o0 = (size_t)(irow0 * BS + b) * DIMM + h * HD;
    const size_t o1 = (size_t)((irow0 + 8) * BS + b) * DIMM + h * HD;
    #pragma unroll
    for (int g = 0; g < 8; g++) {
        int col = g * 8 + 2 * cq;
        store_split(&AVh[o0 + col], &AVl[o0 + col], oacc[g][0] * inv0, oacc[g][1] * inv0);
        store_split(&AVh[o1 + col], &AVl[o1 + col], oacc[g][2] * inv1, oacc[g][3] * inv1);
    }
}

// ---------------------------------------------------------------------------
// Launch
// ---------------------------------------------------------------------------
extern "C" void kernel_launch(void* const* d_in, const int* in_sizes, int n_in,
                              void* d_out, int out_size)
{
    const float* inputs  = (const float*)d_in[0];
    const float* pos_emb = (const float*)d_in[1];
    const float* full_in = (const float*)d_in[2];
    const float* u       = (const float*)d_in[3];
    const float* v       = (const float*)d_in[4];
    const float* W_kv    = (const float*)d_in[5];
    const float* b_kv    = (const float*)d_in[6];
    const float* W_q     = (const float*)d_in[7];
    const float* b_q     = (const float*)d_in[8];
    const float* W_pos   = (const float*)d_in[9];
    const float* b_pos   = (const float*)d_in[10];
    const float* W_proj  = (const float*)d_in[11];
    const float* b_proj  = (const float*)d_in[12];
    float* out = (float*)d_out;

    bf *FIh, *FIl, *INh, *INl, *PEh, *PEl, *Wkvh, *Wkvl, *Wqh, *Wql,
       *Wph, *Wpl, *Wprh, *Wprl, *KVh, *KVl, *Quh, *Qul, *Qvh, *Qvl,
       *Rh, *Rl, *AVh, *AVl;
    float* C2;
    cudaGetSymbolAddress((void**)&FIh, g_FIh);   cudaGetSymbolAddress((void**)&FIl, g_FIl);
    cudaGetSymbolAddress((void**)&INh, g_INh);   cudaGetSymbolAddress((void**)&INl, g_INl);
    cudaGetSymbolAddress((void**)&PEh, g_PEh);   cudaGetSymbolAddress((void**)&PEl, g_PEl);
    cudaGetSymbolAddress((void**)&Wkvh, g_Wkvh); cudaGetSymbolAddress((void**)&Wkvl, g_Wkvl);
    cudaGetSymbolAddress((void**)&Wqh, g_Wqh);   cudaGetSymbolAddress((void**)&Wql, g_Wql);
    cudaGetSymbolAddress((void**)&Wph, g_Wph);   cudaGetSymbolAddress((void**)&Wpl, g_Wpl);
    cudaGetSymbolAddress((void**)&Wprh, g_Wprh); cudaGetSymbolAddress((void**)&Wprl, g_Wprl);
    cudaGetSymbolAddress((void**)&KVh, g_KVh);   cudaGetSymbolAddress((void**)&KVl, g_KVl);
    cudaGetSymbolAddress((void**)&Quh, g_Quh);   cudaGetSymbolAddress((void**)&Qul, g_Qul);
    cudaGetSymbolAddress((void**)&Qvh, g_Qvh);   cudaGetSymbolAddress((void**)&Qvl, g_Qvl);
    cudaGetSymbolAddress((void**)&Rh, g_Rh);     cudaGetSymbolAddress((void**)&Rl, g_Rl);
    cudaGetSymbolAddress((void**)&AVh, g_AVh);   cudaGetSymbolAddress((void**)&AVl, g_AVl);
    cudaGetSymbolAddress((void**)&C2, g_C2);

    // 0. Convert inputs/weights to bf16 hi/lo (once per launch)
    auto cvt = [](const float* x, bf* h, bf* l, int n) {
        cvt_split<<<n / 1024, 256>>>(x, h, l, n);
    };
    cvt(full_in, FIh, FIl, 4194304);
    cvt(inputs,  INh, INl, 2097152);
    cvt(pos_emb, PEh, PEl, 1048576);
    cvt(W_kv,  Wkvh, Wkvl, 2097152);
    cvt(W_q,   Wqh,  Wql,  1048576);
    cvt(W_pos, Wph,  Wpl,  1048576);
    cvt(W_proj, Wprh, Wprl, 1048576);

    // 1. KV = full_input @ W_kv + b_kv -> split bf16 (4096, 2048)
    gemm_bb<1><<<dim3(2048 / 128, 4096 / 128), 256>>>(
        FIh, FIl, Wkvh, Wkvl, b_kv, nullptr, nullptr,
        nullptr, KVh, KVl, nullptr, nullptr, 4096, 2048, 1024);

    // 2. Q GEMM -> Qu and Qv split bf16 (2048, 1024)
    gemm_bb<2><<<dim3(1024 / 128, 2048 / 128), 256>>>(
        INh, INl, Wqh, Wql, b_q, u, v,
        nullptr, Quh, Qul, Qvh, Qvl, 2048, 1024, 1024);

    // 3. R = pos_embedding @ W_pos + b_pos -> split bf16 (1024, 1024)
    gemm_bb<1><<<dim3(1024 / 128, 1024 / 128), 256>>>(
        PEh, PEl, Wph, Wpl, b_pos, nullptr, nullptr,
        nullptr, Rh, Rl, nullptr, nullptr, 1024, 1024, 1024);

    // 4. Position scores
    pos_scores_bb<<<dim3(FULL / 64, CUR / 64, BS * NH), 128>>>(Qvh, Qvl, Rh, Rl, C2);

    // 5. Fused attention
    attn_fused_bb<<<dim3(CUR / 64, BS * NH), 128>>>(Quh, Qul, KVh, KVl, C2, AVh, AVl);

    // 6. out = AV @ W_proj + b_proj (fp32)
    gemm_bb<0><<<dim3(1024 / 128, 2048 / 128), 256>>>(
        AVh, AVl, Wprh, Wprl, b_proj, nullptr, nullptr,
        out, nullptr, nullptr, nullptr, nullptr, 2048, 1024, 1024);
}

// round 7
// speedup vs baseline: 3.5569x; 1.0134x over previous
#include <cuda_runtime.h>
#include <cuda_bf16.h>
#include <cstdint>
#include <cstddef>

#define CUR   512
#define FULL  1024
#define BS    4
#define DIMM  1024
#define NH    16
#define HD    64
#define PREV  512

typedef __nv_bfloat16 bf;

// ---------------- scratch (bf16 hi/lo pairs + fp32 C2) ----------------
__device__ __align__(256) bf g_FIh[4194304], g_FIl[4194304];     // full_input
__device__ __align__(256) bf g_INh[2097152], g_INl[2097152];     // inputs
__device__ __align__(256) bf g_PEh[1048576], g_PEl[1048576];     // pos_embedding
__device__ __align__(256) bf g_Wkvh[2097152], g_Wkvl[2097152];
__device__ __align__(256) bf g_Wqh[1048576],  g_Wql[1048576];
__device__ __align__(256) bf g_Wph[1048576],  g_Wpl[1048576];
__device__ __align__(256) bf g_Wprh[1048576], g_Wprl[1048576];
__device__ __align__(256) bf g_KVh[8388608],  g_KVl[8388608];    // (4096,2048) K|V
__device__ __align__(256) bf g_Quh[2097152],  g_Qul[2097152];    // Q+u
__device__ __align__(256) bf g_Qvh[2097152],  g_Qvl[2097152];    // Q+v
__device__ __align__(256) bf g_Rh[1048576],   g_Rl[1048576];
__device__ __align__(256) bf g_AVh[2097152],  g_AVl[2097152];
__device__ float g_C2[(size_t)BS * NH * CUR * FULL];

// ---------------- helpers ----------------
__device__ __forceinline__ uint32_t smem_u32(const void* p) {
    return (uint32_t)__cvta_generic_to_shared(p);
}
__device__ __forceinline__ void ldsm4(uint32_t* r, uint32_t a) {
    asm volatile("ldmatrix.sync.aligned.m8n8.x4.shared.b16 {%0,%1,%2,%3}, [%4];"
        : "=r"(r[0]), "=r"(r[1]), "=r"(r[2]), "=r"(r[3]) : "r"(a));
}
__device__ __forceinline__ void ldsm4t(uint32_t* r, uint32_t a) {
    asm volatile("ldmatrix.sync.aligned.m8n8.x4.trans.shared.b16 {%0,%1,%2,%3}, [%4];"
        : "=r"(r[0]), "=r"(r[1]), "=r"(r[2]), "=r"(r[3]) : "r"(a));
}
__device__ __forceinline__ void mmabf(float* d, const uint32_t* a, const uint32_t* b) {
    asm volatile(
        "mma.sync.aligned.m16n8k16.row.col.f32.bf16.bf16.f32 "
        "{%0,%1,%2,%3},{%4,%5,%6,%7},{%8,%9},{%0,%1,%2,%3};"
        : "+f"(d[0]), "+f"(d[1]), "+f"(d[2]), "+f"(d[3])
        : "r"(a[0]), "r"(a[1]), "r"(a[2]), "r"(a[3]), "r"(b[0]), "r"(b[1]));
}
__device__ __forceinline__ void store_split(bf* ph, bf* pl, float x, float y) {
    bf hx = __float2bfloat16(x), hy = __float2bfloat16(y);
    __nv_bfloat162 H; H.x = hx; H.y = hy;
    __nv_bfloat162 L;
    L.x = __float2bfloat16(x - __bfloat162float(hx));
    L.y = __float2bfloat16(y - __bfloat162float(hy));
    *(__nv_bfloat162*)ph = H;
    *(__nv_bfloat162*)pl = L;
}
__device__ __forceinline__ void split2(float x, float y, uint32_t& h, uint32_t& l) {
    bf hx = __float2bfloat16(x), hy = __float2bfloat16(y);
    __nv_bfloat162 H; H.x = hx; H.y = hy;
    __nv_bfloat162 L;
    L.x = __float2bfloat16(x - __bfloat162float(hx));
    L.y = __float2bfloat16(y - __bfloat162float(hy));
    h = *reinterpret_cast<uint32_t*>(&H);
    l = *reinterpret_cast<uint32_t*>(&L);
}
#define CPA(dst, src) \
    asm volatile("cp.async.cg.shared.global [%0], [%1], 16;" :: "r"(dst), "l"(src))
#define CPC() asm volatile("cp.async.commit_group;" ::: "memory")
#define CPW(n) asm volatile("cp.async.wait_group %0;" :: "n"(n) : "memory")
__device__ __forceinline__ void cpw_rem(int rem) {
    if (rem >= 2) CPW(2);
    else if (rem == 1) CPW(1);
    else CPW(0);
}

// ---------------- converters ----------------
__global__ __launch_bounds__(256)
void cvt_split(const float* __restrict__ x, bf* __restrict__ h,
               bf* __restrict__ l, int n)
{
    int i = (blockIdx.x * 256 + threadIdx.x) * 4;
    if (i < n) {
        float4 v = *(const float4*)&x[i];
        store_split(&h[i],     &l[i],     v.x, v.y);
        store_split(&h[i + 2], &l[i + 2], v.z, v.w);
    }
}

// ---------------------------------------------------------------------------
// GEMM: C(MxN) = A(MxK)*B(KxN) (+bias). 128x128 tile, BK=32, 256 thr,
// 8 warps (4m x 2n), warp tile 32x64, 3-term hi/lo, 4-stage cp.async pipeline.
// Stage layout (37888B): Ah[128][40] | Al | Bh[32][136] | Bl.
// MODE 0: fp32 out. MODE 1: split bf16 out. MODE 2: dual (bias+u),(bias+v).
// ---------------------------------------------------------------------------
#define GSTAGE 37888
template <int MODE>
__global__ __launch_bounds__(256)
void gemm_ca(const bf* __restrict__ Ah_, const bf* __restrict__ Al_,
             const bf* __restrict__ Bh_, const bf* __restrict__ Bl_,
             const float* __restrict__ bias, const float* __restrict__ uvec,
             const float* __restrict__ vvec,
             float* __restrict__ Cf,
             bf* __restrict__ Xh, bf* __restrict__ Xl,
             bf* __restrict__ Yh, bf* __restrict__ Yl,
             int M, int N, int K)
{
    extern __shared__ char dsm[];
    const int tid = threadIdx.x, lane = tid & 31, wid = tid >> 5;
    const int wm = wid >> 1, wn = wid & 1;
    const int m0 = blockIdx.y * 128, n0 = blockIdx.x * 128;

    const int lam = tid >> 1;                 // A row 0..127
    const int lac = (tid & 1) * 16;           // A col elem (16 elems = 32B)
    const int lbk = tid >> 3;                 // B row 0..31
    const int lbn = (tid & 7) * 16;           // B col elem

    const bf* gAh = Ah_ + (size_t)(m0 + lam) * K + lac;
    const bf* gAl = Al_ + (size_t)(m0 + lam) * K + lac;
    const bf* gBh = Bh_ + (size_t)lbk * N + n0 + lbn;
    const bf* gBl = Bl_ + (size_t)lbk * N + n0 + lbn;

    const uint32_t dA0 = smem_u32(dsm) + lam * 80 + (tid & 1) * 32;
    const uint32_t dB0 = smem_u32(dsm) + 20480 + lbk * 272 + (tid & 7) * 32;

    const int nc = K / 32;

    auto issue = [&](int t) {
        const int s = t & 3;
        const uint32_t da = dA0 + s * GSTAGE;
        const uint32_t db = dB0 + s * GSTAGE;
        const bf* ah = gAh + t * 32;
        const bf* al = gAl + t * 32;
        const bf* bh = gBh + (size_t)t * 32 * N;
        const bf* bl = gBl + (size_t)t * 32 * N;
        CPA(da,          ah);     CPA(da + 16,          ah + 8);
        CPA(da + 10240,  al);     CPA(da + 10240 + 16,  al + 8);
        CPA(db,          bh);     CPA(db + 16,          bh + 8);
        CPA(db + 8704,   bl);     CPA(db + 8704 + 16,   bl + 8);
        CPC();
    };

    issue(0); issue(1); issue(2);

    float acc[2][8][4] = {};

    for (int t = 0; t < nc; t++) {
        cpw_rem(nc - 1 - t);
        __syncthreads();
        if (t + 3 < nc) issue(t + 3);

        char* st = dsm + (t & 3) * GSTAGE;
        bf* sAh = (bf*)st;
        bf* sAl = (bf*)(st + 10240);
        bf* sBh = (bf*)(st + 20480);
        bf* sBl = (bf*)(st + 29184);

        #pragma unroll
        for (int s = 0; s < 2; s++) {
            const int ks = s * 16;
            uint32_t ahf[2][4], alf[2][4], bhf[8][2], blf[8][2];
            #pragma unroll
            for (int f = 0; f < 2; f++) {
                int row = wm * 32 + f * 16 + (lane & 15);
                int kc  = ks + ((lane & 16) >> 1);
                ldsm4(ahf[f], smem_u32(&sAh[row * 40 + kc]));
                ldsm4(alf[f], smem_u32(&sAl[row * 40 + kc]));
            }
            #pragma unroll
            for (int g4 = 0; g4 < 4; g4++) {
                int krow = ks + (lane & 15);
                int ncc  = wn * 64 + g4 * 16 + ((lane & 16) >> 1);
                uint32_t tt[4];
                ldsm4t(tt, smem_u32(&sBh[krow * 136 + ncc]));
                bhf[2*g4][0] = tt[0]; bhf[2*g4][1] = tt[1];
                bhf[2*g4+1][0] = tt[2]; bhf[2*g4+1][1] = tt[3];
                ldsm4t(tt, smem_u32(&sBl[krow * 136 + ncc]));
                blf[2*g4][0] = tt[0]; blf[2*g4][1] = tt[1];
                blf[2*g4+1][0] = tt[2]; blf[2*g4+1][1] = tt[3];
            }
            #pragma unroll
            for (int f = 0; f < 2; f++)
                #pragma unroll
                for (int g = 0; g < 8; g++) {
                    mmabf(acc[f][g], ahf[f], bhf[g]);
                    mmabf(acc[f][g], ahf[f], blf[g]);
                    mmabf(acc[f][g], alf[f], bhf[g]);
                }
        }
    }

    const int r = lane >> 2, c2 = (lane & 3) * 2;
    #pragma unroll
    for (int f = 0; f < 2; f++) {
        int row0 = m0 + wm * 32 + f * 16 + r;
        #pragma unroll
        for (int g = 0; g < 8; g++) {
            int col = n0 + wn * 64 + g * 8 + c2;
            float2 b2 = *(const float2*)&bias[col];
            float v00 = acc[f][g][0] + b2.x, v01 = acc[f][g][1] + b2.y;
            float v10 = acc[f][g][2] + b2.x, v11 = acc[f][g][3] + b2.y;
            size_t i0o = (size_t)row0 * N + col;
            size_t i1o = (size_t)(row0 + 8) * N + col;
            if (MODE == 0) {
                *(float2*)&Cf[i0o] = make_float2(v00, v01);
                *(float2*)&Cf[i1o] = make_float2(v10, v11);
            } else if (MODE == 1) {
                store_split(&Xh[i0o], &Xl[i0o], v00, v01);
                store_split(&Xh[i1o], &Xl[i1o], v10, v11);
            } else {
                float2 uu = *(const float2*)&uvec[col];
                float2 vv = *(const float2*)&vvec[col];
                store_split(&Xh[i0o], &Xl[i0o], v00 + uu.x, v01 + uu.y);
                store_split(&Xh[i1o], &Xl[i1o], v10 + uu.x, v11 + uu.y);
                store_split(&Yh[i0o], &Yl[i0o], v00 + vv.x, v01 + vv.y);
                store_split(&Yh[i1o], &Yl[i1o], v10 + vv.x, v11 + vv.y);
            }
        }
    }
}

// ---------------------------------------------------------------------------
// Position scores: C2[bh,i,k] = Qv[i,b,h,:] . R[k, h*64:+64]. 64x64 tile,
// 128 thr, 4 warps (2x2). (unchanged from R4)
// ---------------------------------------------------------------------------
__global__ __launch_bounds__(128)
void pos_scores_bb(const bf* __restrict__ Qvh, const bf* __restrict__ Qvl,
                   const bf* __restrict__ Rh, const bf* __restrict__ Rl,
                   float* __restrict__ C2)
{
    const int bh = blockIdx.z, b = bh >> 4, h = bh & 15;
    const int i0 = blockIdx.y * 64, n0 = blockIdx.x * 64;
    if (n0 + i0 < 385) return;

    __shared__ bf sQh[64][72], sQl[64][72], sRh[64][72], sRl[64][72];

    const int tid = threadIdx.x, lane = tid & 31, wid = tid >> 5;
    const int wm = wid >> 1, wn = wid & 1;

    {
        const int row = tid >> 1, cb = (tid & 1) * 32;
        const size_t qoff = (size_t)((i0 + row) * BS + b) * DIMM + h * HD + cb;
        const size_t roff = (size_t)(n0 + row) * DIMM + h * HD + cb;
        #pragma unroll
        for (int q = 0; q < 4; q++) {
            *(uint4*)&sQh[row][cb + q * 8] = *(const uint4*)&Qvh[qoff + q * 8];
            *(uint4*)&sQl[row][cb + q * 8] = *(const uint4*)&Qvl[qoff + q * 8];
            *(uint4*)&sRh[row][cb + q * 8] = *(const uint4*)&Rh[roff + q * 8];
            *(uint4*)&sRl[row][cb + q * 8] = *(const uint4*)&Rl[roff + q * 8];
        }
    }
    __syncthreads();

    float acc[2][4][4] = {};
    #pragma unroll
    for (int s = 0; s < 4; s++) {
        const int ks = s * 16;
        uint32_t ah[2][4], al[2][4], bh2[4][2], bl2[4][2];
        #pragma unroll
        for (int f = 0; f < 2; f++) {
            int row = wm * 32 + f * 16 + (lane & 15);
            int kc  = ks + ((lane & 16) >> 1);
            ldsm4(ah[f], smem_u32(&sQh[row][kc]));
            ldsm4(al[f], smem_u32(&sQl[row][kc]));
        }
        #pragma unroll
        for (int g4 = 0; g4 < 2; g4++) {
            int nrow = wn * 32 + g4 * 16 + (lane & 15);
            int kc   = ks + ((lane & 16) >> 1);
            uint32_t t[4];
            ldsm4(t, smem_u32(&sRh[nrow][kc]));
            bh2[2*g4][0] = t[0]; bh2[2*g4+1][0] = t[1];
            bh2[2*g4][1] = t[2]; bh2[2*g4+1][1] = t[3];
            ldsm4(t, smem_u32(&sRl[nrow][kc]));
            bl2[2*g4][0] = t[0]; bl2[2*g4+1][0] = t[1];
            bl2[2*g4][1] = t[2]; bl2[2*g4+1][1] = t[3];
        }
        #pragma unroll
        for (int f = 0; f < 2; f++)
            #pragma unroll
            for (int g = 0; g < 4; g++) {
                mmabf(acc[f][g], ah[f], bh2[g]);
                mmabf(acc[f][g], ah[f], bl2[g]);
                mmabf(acc[f][g], al[f], bh2[g]);
            }
    }

    const int r = lane >> 2, c2 = (lane & 3) * 2;
    float* out = C2 + (size_t)bh * CUR * FULL;
    #pragma unroll
    for (int f = 0; f < 2; f++) {
        int row0 = i0 + wm * 32 + f * 16 + r;
        #pragma unroll
        for (int g = 0; g < 4; g++) {
            int col = n0 + wn * 32 + g * 8 + c2;
            *(float2*)&out[(size_t)row0 * FULL + col]       = make_float2(acc[f][g][0], acc[f][g][1]);
            *(float2*)&out[(size_t)(row0 + 8) * FULL + col] = make_float2(acc[f][g][2], acc[f][g][3]);
        }
    }
}

// ---------------------------------------------------------------------------
// Fused attention with 2-stage cp.async K/V pipeline. 64 rows/block, 128 thr.
// Dynamic smem: 2 stages x {Kh,Kl,Vh,Vl each [64][72] bf16} = 73728 B.
// Static smem: Qh/Ql.
// ---------------------------------------------------------------------------
#define ASTAGE 36864
__global__ __launch_bounds__(128)
void attn_ca(const bf* __restrict__ Quh, const bf* __restrict__ Qul,
             const bf* __restrict__ KVh, const bf* __restrict__ KVl,
             const float* __restrict__ C2,
             bf* __restrict__ AVh, bf* __restrict__ AVl)
{
    extern __shared__ char dsm[];
    __shared__ bf Qh_s[64][72], Ql_s[64][72];

    const int bh = blockIdx.y, b = bh >> 4, h = bh & 15;
    const int i0 = blockIdx.x * 64;

    const int tid = threadIdx.x, lane = tid & 31, w = tid >> 5;
    const int r = lane >> 2, cq = lane & 3;
    const int ii = tid >> 1, cb = (tid & 1) * 32;

    const int jtiles = i0 / 64 + 9;

    auto issue_kv = [&](int jt) {
        char* st = dsm + (jt & 1) * ASTAGE;
        const size_t koff = (size_t)((jt * 64 + ii) * BS + b) * (2 * DIMM) + h * HD + cb;
        const char* gKh = (const char*)(KVh + koff);
        const char* gKl = (const char*)(KVl + koff);
        const char* gVh = (const char*)(KVh + koff + DIMM);
        const char* gVl = (const char*)(KVl + koff + DIMM);
        const uint32_t d = smem_u32(st) + ii * 144 + (tid & 1) * 64;
        #pragma unroll
        for (int c = 0; c < 4; c++) {
            CPA(d +         c * 16, gKh + c * 16);
            CPA(d + 9216  + c * 16, gKl + c * 16);
            CPA(d + 18432 + c * 16, gVh + c * 16);
            CPA(d + 27648 + c * 16, gVl + c * 16);
        }
        CPC();
    };

    // Load Q tiles (plain) and start K/V stage 0
    issue_kv(0);
    {
        const size_t qoff = (size_t)((i0 + ii) * BS + b) * DIMM + h * HD + cb;
        #pragma unroll
        for (int q = 0; q < 4; q++) {
            *(uint4*)&Qh_s[ii][cb + q * 8] = *(const uint4*)&Quh[qoff + q * 8];
            *(uint4*)&Ql_s[ii][cb + q * 8] = *(const uint4*)&Qul[qoff + q * 8];
        }
    }
    __syncthreads();

    uint32_t qh[4][4], ql[4][4];
    #pragma unroll
    for (int s = 0; s < 4; s++) {
        int rowi = w * 16 + (lane & 15);
        int kc  = s * 16 + ((lane & 16) >> 1);
        ldsm4(qh[s], smem_u32(&Qh_s[rowi][kc]));
        ldsm4(ql[s], smem_u32(&Ql_s[rowi][kc]));
    }

    float oacc[8][4] = {};
    float m0 = -1e30f, m1 = -1e30f, l0 = 0.f, l1 = 0.f;

    const int irow0 = i0 + w * 16 + r;
    const float* c2row0 = C2 + ((size_t)bh * CUR + irow0) * FULL;
    const float* c2row1 = c2row0 + (size_t)8 * FULL;

    for (int jt = 0; jt < jtiles; jt++) {
        const int j0 = jt * 64;
        CPW(0);
        __syncthreads();
        if (jt + 1 < jtiles) issue_kv(jt + 1);

        char* st = dsm + (jt & 1) * ASTAGE;
        bf* Kh_s = (bf*)st;
        bf* Kl_s = (bf*)(st + 9216);
        bf* Vh_s = (bf*)(st + 18432);
        bf* Vl_s = (bf*)(st + 27648);

        float sacc[8][4] = {};
        #pragma unroll
        for (int s = 0; s < 4; s++) {
            const int ks = s * 16;
            uint32_t bhf[8][2], blf[8][2];
            #pragma unroll
            for (int g4 = 0; g4 < 4; g4++) {
                int nrow = g4 * 16 + (lane & 15);
                int kc   = ks + ((lane & 16) >> 1);
                uint32_t t[4];
                ldsm4(t, smem_u32(&Kh_s[nrow * 72 + kc]));
                bhf[2*g4][0] = t[0]; bhf[2*g4+1][0] = t[1];
                bhf[2*g4][1] = t[2]; bhf[2*g4+1][1] = t[3];
                ldsm4(t, smem_u32(&Kl_s[nrow * 72 + kc]));
                blf[2*g4][0] = t[0]; blf[2*g4+1][0] = t[1];
                blf[2*g4][1] = t[2]; blf[2*g4+1][1] = t[3];
            }
            #pragma unroll
            for (int g = 0; g < 8; g++) {
                mmabf(sacc[g], qh[s], bhf[g]);
                mmabf(sacc[g], qh[s], blf[g]);
                mmabf(sacc[g], ql[s], bhf[g]);
            }
        }

        const bool boundary = (j0 == i0 + PREV);
        #pragma unroll
        for (int g = 0; g < 8; g++) {
            int jg  = j0 + g * 8 + 2 * cq;
            int k00 = jg - irow0 + 511;
            int k10 = k00 - 8;
            if (!boundary) {
                sacc[g][0] = 0.125f * (sacc[g][0] + c2row0[k00]);
                sacc[g][1] = 0.125f * (sacc[g][1] + c2row0[k00 + 1]);
                sacc[g][2] = 0.125f * (sacc[g][2] + c2row1[k10]);
                sacc[g][3] = 0.125f * (sacc[g][3] + c2row1[k10 + 1]);
            } else {
                sacc[g][0] = (k00     <= 1023) ? 0.125f * (sacc[g][0] + c2row0[k00])     : -1e30f;
                sacc[g][1] = (k00 + 1 <= 1023) ? 0.125f * (sacc[g][1] + c2row0[k00 + 1]) : -1e30f;
                sacc[g][2] = (k10     <= 1023) ? 0.125f * (sacc[g][2] + c2row1[k10])     : -1e30f;
                sacc[g][3] = (k10 + 1 <= 1023) ? 0.125f * (sacc[g][3] + c2row1[k10 + 1]) : -1e30f;
            }
        }

        float mx0 = -1e30f, mx1 = -1e30f;
        #pragma unroll
        for (int g = 0; g < 8; g++) {
            mx0 = fmaxf(mx0, fmaxf(sacc[g][0], sacc[g][1]));
            mx1 = fmaxf(mx1, fmaxf(sacc[g][2], sacc[g][3]));
        }
        mx0 = fmaxf(mx0, __shfl_xor_sync(0xffffffffu, mx0, 1));
        mx0 = fmaxf(mx0, __shfl_xor_sync(0xffffffffu, mx0, 2));
        mx1 = fmaxf(mx1, __shfl_xor_sync(0xffffffffu, mx1, 1));
        mx1 = fmaxf(mx1, __shfl_xor_sync(0xffffffffu, mx1, 2));

        float mn0 = fmaxf(m0, mx0), mn1 = fmaxf(m1, mx1);
        float a0 = __expf(m0 - mn0), a1 = __expf(m1 - mn1);
        m0 = mn0; m1 = mn1;
        l0 *= a0; l1 *= a1;
        #pragma unroll
        for (int g = 0; g < 8; g++) {
            oacc[g][0] *= a0; oacc[g][1] *= a0;
            oacc[g][2] *= a1; oacc[g][3] *= a1;
        }

        float p[8][4];
        #pragma unroll
        for (int g = 0; g < 8; g++) {
            p[g][0] = __expf(sacc[g][0] - m0);
            p[g][1] = __expf(sacc[g][1] - m0);
            p[g][2] = __expf(sacc[g][2] - m1);
            p[g][3] = __expf(sacc[g][3] - m1);
            l0 += p[g][0] + p[g][1];
            l1 += p[g][2] + p[g][3];
        }

        #pragma unroll
        for (int t4 = 0; t4 < 4; t4++) {
            uint32_t pah[4], pal[4];
            split2(p[2*t4][0],   p[2*t4][1],   pah[0], pal[0]);
            split2(p[2*t4][2],   p[2*t4][3],   pah[1], pal[1]);
            split2(p[2*t4+1][0], p[2*t4+1][1], pah[2], pal[2]);
            split2(p[2*t4+1][2], p[2*t4+1][3], pah[3], pal[3]);

            uint32_t vhf[8][2], vlf[8][2];
            #pragma unroll
            for (int g4 = 0; g4 < 4; g4++) {
                int krow = t4 * 16 + (lane & 15);
                int ncc  = g4 * 16 + ((lane & 16) >> 1);
                uint32_t t[4];
                ldsm4t(t, smem_u32(&Vh_s[krow * 72 + ncc]));
                vhf[2*g4][0] = t[0]; vhf[2*g4][1] = t[1];
                vhf[2*g4+1][0] = t[2]; vhf[2*g4+1][1] = t[3];
                ldsm4t(t, smem_u32(&Vl_s[krow * 72 + ncc]));
                vlf[2*g4][0] = t[0]; vlf[2*g4][1] = t[1];
                vlf[2*g4+1][0] = t[2]; vlf[2*g4+1][1] = t[3];
            }
            #pragma unroll
            for (int g = 0; g < 8; g++) {
                mmabf(oacc[g], pah, vhf[g]);
                mmabf(oacc[g], pah, vlf[g]);
                mmabf(oacc[g], pal, vhf[g]);
            }
        }
    }

    l0 += __shfl_xor_sync(0xffffffffu, l0, 1);
    l0 += __shfl_xor_sync(0xffffffffu, l0, 2);
    l1 += __shfl_xor_sync(0xffffffffu, l1, 1);
    l1 += __shfl_xor_sync(0xffffffffu, l1, 2);
    const float inv0 = 1.f / l0, inv1 = 1.f / l1;

    const size_t o0 = (size_t)(irow0 * BS + b) * DIMM + h * HD;
    const size_t o1 = (size_t)((irow0 + 8) * BS + b) * DIMM + h * HD;
    #pragma unroll
    for (int g = 0; g < 8; g++) {
        int col = g * 8 + 2 * cq;
        store_split(&AVh[o0 + col], &AVl[o0 + col], oacc[g][0] * inv0, oacc[g][1] * inv0);
        store_split(&AVh[o1 + col], &AVl[o1 + col], oacc[g][2] * inv1, oacc[g][3] * inv1);
    }
}

// ---------------------------------------------------------------------------
// Launch
// ---------------------------------------------------------------------------
extern "C" void kernel_launch(void* const* d_in, const int* in_sizes, int n_in,
                              void* d_out, int out_size)
{
    const float* inputs  = (const float*)d_in[0];
    const float* pos_emb = (const float*)d_in[1];
    const float* full_in = (const float*)d_in[2];
    const float* u       = (const float*)d_in[3];
    const float* v       = (const float*)d_in[4];
    const float* W_kv    = (const float*)d_in[5];
    const float* b_kv    = (const float*)d_in[6];
    const float* W_q     = (const float*)d_in[7];
    const float* b_q     = (const float*)d_in[8];
    const float* W_pos   = (const float*)d_in[9];
    const float* b_pos   = (const float*)d_in[10];
    const float* W_proj  = (const float*)d_in[11];
    const float* b_proj  = (const float*)d_in[12];
    float* out = (float*)d_out;

    bf *FIh, *FIl, *INh, *INl, *PEh, *PEl, *Wkvh, *Wkvl, *Wqh, *Wql,
       *Wph, *Wpl, *Wprh, *Wprl, *KVh, *KVl, *Quh, *Qul, *Qvh, *Qvl,
       *Rh, *Rl, *AVh, *AVl;
    float* C2;
    cudaGetSymbolAddress((void**)&FIh, g_FIh);   cudaGetSymbolAddress((void**)&FIl, g_FIl);
    cudaGetSymbolAddress((void**)&INh, g_INh);   cudaGetSymbolAddress((void**)&INl, g_INl);
    cudaGetSymbolAddress((void**)&PEh, g_PEh);   cudaGetSymbolAddress((void**)&PEl, g_PEl);
    cudaGetSymbolAddress((void**)&Wkvh, g_Wkvh); cudaGetSymbolAddress((void**)&Wkvl, g_Wkvl);
    cudaGetSymbolAddress((void**)&Wqh, g_Wqh);   cudaGetSymbolAddress((void**)&Wql, g_Wql);
    cudaGetSymbolAddress((void**)&Wph, g_Wph);   cudaGetSymbolAddress((void**)&Wpl, g_Wpl);
    cudaGetSymbolAddress((void**)&Wprh, g_Wprh); cudaGetSymbolAddress((void**)&Wprl, g_Wprl);
    cudaGetSymbolAddress((void**)&KVh, g_KVh);   cudaGetSymbolAddress((void**)&KVl, g_KVl);
    cudaGetSymbolAddress((void**)&Quh, g_Quh);   cudaGetSymbolAddress((void**)&Qul, g_Qul);
    cudaGetSymbolAddress((void**)&Qvh, g_Qvh);   cudaGetSymbolAddress((void**)&Qvl, g_Qvl);
    cudaGetSymbolAddress((void**)&Rh, g_Rh);     cudaGetSymbolAddress((void**)&Rl, g_Rl);
    cudaGetSymbolAddress((void**)&AVh, g_AVh);   cudaGetSymbolAddress((void**)&AVl, g_AVl);
    cudaGetSymbolAddress((void**)&C2, g_C2);

    const int GSM = 4 * GSTAGE;     // 151552
    const int ASM = 2 * ASTAGE;     // 73728
    cudaFuncSetAttribute(gemm_ca<0>, cudaFuncAttributeMaxDynamicSharedMemorySize, GSM);
    cudaFuncSetAttribute(gemm_ca<1>, cudaFuncAttributeMaxDynamicSharedMemorySize, GSM);
    cudaFuncSetAttribute(gemm_ca<2>, cudaFuncAttributeMaxDynamicSharedMemorySize, GSM);
    cudaFuncSetAttribute(attn_ca,    cudaFuncAttributeMaxDynamicSharedMemorySize, ASM);

    // 0. Conversions
    cvt_split<<<4194304 / 1024, 256>>>(full_in, FIh, FIl, 4194304);
    cvt_split<<<2097152 / 1024, 256>>>(inputs,  INh, INl, 2097152);
    cvt_split<<<1048576 / 1024, 256>>>(pos_emb, PEh, PEl, 1048576);
    cvt_split<<<2097152 / 1024, 256>>>(W_kv,  Wkvh, Wkvl, 2097152);
    cvt_split<<<1048576 / 1024, 256>>>(W_q,   Wqh,  Wql,  1048576);
    cvt_split<<<1048576 / 1024, 256>>>(W_pos, Wph,  Wpl,  1048576);
    cvt_split<<<1048576 / 1024, 256>>>(W_proj, Wprh, Wprl, 1048576);

    // 1. KV = full_input @ W_kv + b_kv -> split bf16 (4096, 2048)
    gemm_ca<1><<<dim3(16, 32), 256, GSM>>>(
        FIh, FIl, Wkvh, Wkvl, b_kv, nullptr, nullptr,
        nullptr, KVh, KVl, nullptr, nullptr, 4096, 2048, 1024);

    // 2. Q GEMM -> Qu, Qv split bf16 (2048, 1024)
    gemm_ca<2><<<dim3(8, 16), 256, GSM>>>(
        INh, INl, Wqh, Wql, b_q, u, v,
        nullptr, Quh, Qul, Qvh, Qvl, 2048, 1024, 1024);

    // 3. R = pos_embedding @ W_pos + b_pos -> split bf16 (1024, 1024)
    gemm_ca<1><<<dim3(8, 8), 256, GSM>>>(
        PEh, PEl, Wph, Wpl, b_pos, nullptr, nullptr,
        nullptr, Rh, Rl, nullptr, nullptr, 1024, 1024, 1024);

    // 4. Position scores
    pos_scores_bb<<<dim3(FULL / 64, CUR / 64, BS * NH), 128>>>(Qvh, Qvl, Rh, Rl, C2);

    // 5. Fused attention
    attn_ca<<<dim3(CUR / 64, BS * NH), 128, ASM>>>(Quh, Qul, KVh, KVl, C2, AVh, AVl);

    // 6. out = AV @ W_proj + b_proj (fp32)
    gemm_ca<0><<<dim3(8, 16), 256, GSM>>>(
        AVh, AVl, Wprh, Wprl, b_proj, nullptr, nullptr,
        out, nullptr, nullptr, nullptr, nullptr, 2048, 1024, 1024);
}

// round 8
// speedup vs baseline: 3.8234x; 1.0749x over previous
#include <cuda_runtime.h>
#include <cuda_bf16.h>
#include <cstdint>
#include <cstddef>

#define CUR   512
#define FULL  1024
#define BS    4
#define DIMM  1024
#define NH    16
#define HD    64
#define PREV  512

typedef __nv_bfloat16 bf;

// ---------------- scratch (bf16 hi/lo pairs + fp32 C2) ----------------
__device__ __align__(256) bf g_FIh[4194304], g_FIl[4194304];     // full_input
__device__ __align__(256) bf g_INh[2097152], g_INl[2097152];     // inputs
__device__ __align__(256) bf g_PEh[1048576], g_PEl[1048576];     // pos_embedding
__device__ __align__(256) bf g_Wkvh[2097152], g_Wkvl[2097152];
__device__ __align__(256) bf g_Wqh[1048576],  g_Wql[1048576];
__device__ __align__(256) bf g_Wph[1048576],  g_Wpl[1048576];
__device__ __align__(256) bf g_Wprh[1048576], g_Wprl[1048576];
__device__ __align__(256) bf g_KVh[8388608],  g_KVl[8388608];    // (4096,2048) K|V
__device__ __align__(256) bf g_Quh[2097152],  g_Qul[2097152];    // 0.125*(Q+u)
__device__ __align__(256) bf g_Qvh[2097152],  g_Qvl[2097152];    // 0.125*(Q+v)
__device__ __align__(256) bf g_Rh[1048576],   g_Rl[1048576];
__device__ __align__(256) bf g_AVh[2097152],  g_AVl[2097152];
__device__ float g_C2[(size_t)BS * NH * CUR * FULL];
__device__ float g_scr[32];

// ---------------- helpers ----------------
__device__ __forceinline__ uint32_t smem_u32(const void* p) {
    return (uint32_t)__cvta_generic_to_shared(p);
}
__device__ __forceinline__ void ldsm4(uint32_t* r, uint32_t a) {
    asm volatile("ldmatrix.sync.aligned.m8n8.x4.shared.b16 {%0,%1,%2,%3}, [%4];"
        : "=r"(r[0]), "=r"(r[1]), "=r"(r[2]), "=r"(r[3]) : "r"(a));
}
__device__ __forceinline__ void ldsm4t(uint32_t* r, uint32_t a) {
    asm volatile("ldmatrix.sync.aligned.m8n8.x4.trans.shared.b16 {%0,%1,%2,%3}, [%4];"
        : "=r"(r[0]), "=r"(r[1]), "=r"(r[2]), "=r"(r[3]) : "r"(a));
}
__device__ __forceinline__ void mmabf(float* d, const uint32_t* a, const uint32_t* b) {
    asm volatile(
        "mma.sync.aligned.m16n8k16.row.col.f32.bf16.bf16.f32 "
        "{%0,%1,%2,%3},{%4,%5,%6,%7},{%8,%9},{%0,%1,%2,%3};"
        : "+f"(d[0]), "+f"(d[1]), "+f"(d[2]), "+f"(d[3])
        : "r"(a[0]), "r"(a[1]), "r"(a[2]), "r"(a[3]), "r"(b[0]), "r"(b[1]));
}
__device__ __forceinline__ void store_split(bf* ph, bf* pl, float x, float y) {
    bf hx = __float2bfloat16(x), hy = __float2bfloat16(y);
    __nv_bfloat162 H; H.x = hx; H.y = hy;
    __nv_bfloat162 L;
    L.x = __float2bfloat16(x - __bfloat162float(hx));
    L.y = __float2bfloat16(y - __bfloat162float(hy));
    *(__nv_bfloat162*)ph = H;
    *(__nv_bfloat162*)pl = L;
}
__device__ __forceinline__ void split2(float x, float y, uint32_t& h, uint32_t& l) {
    bf hx = __float2bfloat16(x), hy = __float2bfloat16(y);
    __nv_bfloat162 H; H.x = hx; H.y = hy;
    __nv_bfloat162 L;
    L.x = __float2bfloat16(x - __bfloat162float(hx));
    L.y = __float2bfloat16(y - __bfloat162float(hy));
    h = *reinterpret_cast<uint32_t*>(&H);
    l = *reinterpret_cast<uint32_t*>(&L);
}
#define CPA(dst, src) \
    asm volatile("cp.async.cg.shared.global [%0], [%1], 16;" :: "r"(dst), "l"(src))
#define CPC() asm volatile("cp.async.commit_group;" ::: "memory")
#define CPW(n) asm volatile("cp.async.wait_group %0;" :: "n"(n) : "memory")
__device__ __forceinline__ void cpw_rem(int rem) {
    if (rem >= 2) CPW(2);
    else if (rem == 1) CPW(1);
    else CPW(0);
}

// ---------------- dummy (profiling alignment) ----------------
__global__ void dummy_k(float* p) {
    if (threadIdx.x == 0) p[blockIdx.x] = 0.f;
}

// ---------------- merged converter ----------------
struct CT {
    const float* s[7];
    bf* h[7];
    bf* l[7];
    int end[7];
};
__global__ __launch_bounds__(256)
void cvt_mega(CT c)
{
    const int bid = blockIdx.x;
    int ti = 0;
    #pragma unroll
    for (int k = 0; k < 6; k++) ti += (bid >= c.end[k]) ? 1 : 0;
    const int base = ti ? c.end[ti - 1] : 0;
    const int i = ((bid - base) * 256 + threadIdx.x) * 4;
    const float* x = c.s[ti];
    float4 v = *(const float4*)&x[i];
    store_split(&c.h[ti][i],     &c.l[ti][i],     v.x, v.y);
    store_split(&c.h[ti][i + 2], &c.l[ti][i + 2], v.z, v.w);
}

// ---------------------------------------------------------------------------
// Mega GEMM: up to 3 tasks in one launch, dispatched by linear block id.
// Per task: C(Mx N) = A*B (+bias). 128x128 tile, BK=32, 256 thr, 8 warps
// (4m x 2n), warp tile 32x64, 3-term hi/lo, 4-stage cp.async pipeline.
// mode 0: fp32 out. mode 1: split bf16 out. mode 2: dual 0.125*(bias+u/v).
// ---------------------------------------------------------------------------
struct GTask {
    const bf *Ah, *Al, *Bh, *Bl;
    const float *bias, *uvec, *vvec;
    float* Cf;
    bf *Xh, *Xl, *Yh, *Yl;
    int N, K, nbx, mode;
};
struct GT3 { GTask t[3]; int end0, end1; };

#define GSTAGE 37888
__global__ __launch_bounds__(256)
void gemm_mega(GT3 ts)
{
    extern __shared__ char dsm[];
    const int bid = blockIdx.x;
    const int ti = (bid >= ts.end0 ? 1 : 0) + (bid >= ts.end1 ? 1 : 0);
    const GTask T = ts.t[ti];
    const int base = (ti == 0) ? 0 : (ti == 1 ? ts.end0 : ts.end1);
    const int local = bid - base;
    const int by = local / T.nbx, bx = local - by * T.nbx;

    const int tid = threadIdx.x, lane = tid & 31, wid = tid >> 5;
    const int wm = wid >> 1, wn = wid & 1;
    const int m0 = by * 128, n0 = bx * 128;
    const int N = T.N, K = T.K;

    const int lam = tid >> 1;
    const int lac = (tid & 1) * 16;
    const int lbk = tid >> 3;
    const int lbn = (tid & 7) * 16;

    const bf* gAh = T.Ah + (size_t)(m0 + lam) * K + lac;
    const bf* gAl = T.Al + (size_t)(m0 + lam) * K + lac;
    const bf* gBh = T.Bh + (size_t)lbk * N + n0 + lbn;
    const bf* gBl = T.Bl + (size_t)lbk * N + n0 + lbn;

    const uint32_t dA0 = smem_u32(dsm) + lam * 80 + (tid & 1) * 32;
    const uint32_t dB0 = smem_u32(dsm) + 20480 + lbk * 272 + (tid & 7) * 32;

    const int nc = K / 32;

    auto issue = [&](int t) {
        const int s = t & 3;
        const uint32_t da = dA0 + s * GSTAGE;
        const uint32_t db = dB0 + s * GSTAGE;
        const bf* ah = gAh + t * 32;
        const bf* al = gAl + t * 32;
        const bf* bh = gBh + (size_t)t * 32 * N;
        const bf* bl = gBl + (size_t)t * 32 * N;
        CPA(da,          ah);     CPA(da + 16,          ah + 8);
        CPA(da + 10240,  al);     CPA(da + 10240 + 16,  al + 8);
        CPA(db,          bh);     CPA(db + 16,          bh + 8);
        CPA(db + 8704,   bl);     CPA(db + 8704 + 16,   bl + 8);
        CPC();
    };

    issue(0); issue(1); issue(2);

    float acc[2][8][4] = {};

    for (int t = 0; t < nc; t++) {
        cpw_rem(nc - 1 - t);
        __syncthreads();
        if (t + 3 < nc) issue(t + 3);

        char* st = dsm + (t & 3) * GSTAGE;
        bf* sAh = (bf*)st;
        bf* sAl = (bf*)(st + 10240);
        bf* sBh = (bf*)(st + 20480);
        bf* sBl = (bf*)(st + 29184);

        #pragma unroll
        for (int s = 0; s < 2; s++) {
            const int ks = s * 16;
            uint32_t ahf[2][4], alf[2][4], bhf[8][2], blf[8][2];
            #pragma unroll
            for (int f = 0; f < 2; f++) {
                int row = wm * 32 + f * 16 + (lane & 15);
                int kc  = ks + ((lane & 16) >> 1);
                ldsm4(ahf[f], smem_u32(&sAh[row * 40 + kc]));
                ldsm4(alf[f], smem_u32(&sAl[row * 40 + kc]));
            }
            #pragma unroll
            for (int g4 = 0; g4 < 4; g4++) {
                int krow = ks + (lane & 15);
                int ncc  = wn * 64 + g4 * 16 + ((lane & 16) >> 1);
                uint32_t tt[4];
                ldsm4t(tt, smem_u32(&sBh[krow * 136 + ncc]));
                bhf[2*g4][0] = tt[0]; bhf[2*g4][1] = tt[1];
                bhf[2*g4+1][0] = tt[2]; bhf[2*g4+1][1] = tt[3];
                ldsm4t(tt, smem_u32(&sBl[krow * 136 + ncc]));
                blf[2*g4][0] = tt[0]; blf[2*g4][1] = tt[1];
                blf[2*g4+1][0] = tt[2]; blf[2*g4+1][1] = tt[3];
            }
            #pragma unroll
            for (int f = 0; f < 2; f++)
                #pragma unroll
                for (int g = 0; g < 8; g++) {
                    mmabf(acc[f][g], ahf[f], bhf[g]);
                    mmabf(acc[f][g], ahf[f], blf[g]);
                    mmabf(acc[f][g], alf[f], bhf[g]);
                }
        }
    }

    const int r = lane >> 2, c2 = (lane & 3) * 2;
    #pragma unroll
    for (int f = 0; f < 2; f++) {
        int row0 = m0 + wm * 32 + f * 16 + r;
        #pragma unroll
        for (int g = 0; g < 8; g++) {
            int col = n0 + wn * 64 + g * 8 + c2;
            float2 b2 = *(const float2*)&T.bias[col];
            float v00 = acc[f][g][0] + b2.x, v01 = acc[f][g][1] + b2.y;
            float v10 = acc[f][g][2] + b2.x, v11 = acc[f][g][3] + b2.y;
            size_t i0o = (size_t)row0 * N + col;
            size_t i1o = (size_t)(row0 + 8) * N + col;
            if (T.mode == 0) {
                *(float2*)&T.Cf[i0o] = make_float2(v00, v01);
                *(float2*)&T.Cf[i1o] = make_float2(v10, v11);
            } else if (T.mode == 1) {
                store_split(&T.Xh[i0o], &T.Xl[i0o], v00, v01);
                store_split(&T.Xh[i1o], &T.Xl[i1o], v10, v11);
            } else {
                float2 uu = *(const float2*)&T.uvec[col];
                float2 vv = *(const float2*)&T.vvec[col];
                store_split(&T.Xh[i0o], &T.Xl[i0o], 0.125f*(v00 + uu.x), 0.125f*(v01 + uu.y));
                store_split(&T.Xh[i1o], &T.Xl[i1o], 0.125f*(v10 + uu.x), 0.125f*(v11 + uu.y));
                store_split(&T.Yh[i0o], &T.Yl[i0o], 0.125f*(v00 + vv.x), 0.125f*(v01 + vv.y));
                store_split(&T.Yh[i1o], &T.Yl[i1o], 0.125f*(v10 + vv.x), 0.125f*(v11 + vv.y));
            }
        }
    }
}

// ---------------------------------------------------------------------------
// Position scores: C2[bh,i,k] = Qv[i,b,h,:] . R[k, h*64:+64] (pre-scaled).
// ---------------------------------------------------------------------------
__global__ __launch_bounds__(128)
void pos_scores_bb(const bf* __restrict__ Qvh, const bf* __restrict__ Qvl,
                   const bf* __restrict__ Rh, const bf* __restrict__ Rl,
                   float* __restrict__ C2)
{
    const int bh = blockIdx.z, b = bh >> 4, h = bh & 15;
    const int i0 = blockIdx.y * 64, n0 = blockIdx.x * 64;
    if (n0 + i0 < 385) return;

    __shared__ bf sQh[64][72], sQl[64][72], sRh[64][72], sRl[64][72];

    const int tid = threadIdx.x, lane = tid & 31, wid = tid >> 5;
    const int wm = wid >> 1, wn = wid & 1;

    {
        const int row = tid >> 1, cb = (tid & 1) * 32;
        const size_t qoff = (size_t)((i0 + row) * BS + b) * DIMM + h * HD + cb;
        const size_t roff = (size_t)(n0 + row) * DIMM + h * HD + cb;
        #pragma unroll
        for (int q = 0; q < 4; q++) {
            *(uint4*)&sQh[row][cb + q * 8] = *(const uint4*)&Qvh[qoff + q * 8];
            *(uint4*)&sQl[row][cb + q * 8] = *(const uint4*)&Qvl[qoff + q * 8];
            *(uint4*)&sRh[row][cb + q * 8] = *(const uint4*)&Rh[roff + q * 8];
            *(uint4*)&sRl[row][cb + q * 8] = *(const uint4*)&Rl[roff + q * 8];
        }
    }
    __syncthreads();

    float acc[2][4][4] = {};
    #pragma unroll
    for (int s = 0; s < 4; s++) {
        const int ks = s * 16;
        uint32_t ah[2][4], al[2][4], bh2[4][2], bl2[4][2];
        #pragma unroll
        for (int f = 0; f < 2; f++) {
            int row = wm * 32 + f * 16 + (lane & 15);
            int kc  = ks + ((lane & 16) >> 1);
            ldsm4(ah[f], smem_u32(&sQh[row][kc]));
            ldsm4(al[f], smem_u32(&sQl[row][kc]));
        }
        #pragma unroll
        for (int g4 = 0; g4 < 2; g4++) {
            int nrow = wn * 32 + g4 * 16 + (lane & 15);
            int kc   = ks + ((lane & 16) >> 1);
            uint32_t t[4];
            ldsm4(t, smem_u32(&sRh[nrow][kc]));
            bh2[2*g4][0] = t[0]; bh2[2*g4+1][0] = t[1];
            bh2[2*g4][1] = t[2]; bh2[2*g4+1][1] = t[3];
            ldsm4(t, smem_u32(&sRl[nrow][kc]));
            bl2[2*g4][0] = t[0]; bl2[2*g4+1][0] = t[1];
            bl2[2*g4][1] = t[2]; bl2[2*g4+1][1] = t[3];
        }
        #pragma unroll
        for (int f = 0; f < 2; f++)
            #pragma unroll
            for (int g = 0; g < 4; g++) {
                mmabf(acc[f][g], ah[f], bh2[g]);
                mmabf(acc[f][g], ah[f], bl2[g]);
                mmabf(acc[f][g], al[f], bh2[g]);
            }
    }

    const int r = lane >> 2, c2 = (lane & 3) * 2;
    float* out = C2 + (size_t)bh * CUR * FULL;
    #pragma unroll
    for (int f = 0; f < 2; f++) {
        int row0 = i0 + wm * 32 + f * 16 + r;
        #pragma unroll
        for (int g = 0; g < 4; g++) {
            int col = n0 + wn * 32 + g * 8 + c2;
            *(float2*)&out[(size_t)row0 * FULL + col]       = make_float2(acc[f][g][0], acc[f][g][1]);
            *(float2*)&out[(size_t)(row0 + 8) * FULL + col] = make_float2(acc[f][g][2], acc[f][g][3]);
        }
    }
}

// ---------------------------------------------------------------------------
// Fused attention (scores pre-scaled by 0.125 via Qu/Qv/C2).
// ---------------------------------------------------------------------------
#define ASTAGE 36864
__global__ __launch_bounds__(128)
void attn_ca(const bf* __restrict__ Quh, const bf* __restrict__ Qul,
             const bf* __restrict__ KVh, const bf* __restrict__ KVl,
             const float* __restrict__ C2,
             bf* __restrict__ AVh, bf* __restrict__ AVl)
{
    extern __shared__ char dsm[];
    __shared__ bf Qh_s[64][72], Ql_s[64][72];

    const int bh = blockIdx.y, b = bh >> 4, h = bh & 15;
    const int i0 = blockIdx.x * 64;

    const int tid = threadIdx.x, lane = tid & 31, w = tid >> 5;
    const int r = lane >> 2, cq = lane & 3;
    const int ii = tid >> 1, cb = (tid & 1) * 32;

    const int jtiles = i0 / 64 + 9;

    auto issue_kv = [&](int jt) {
        char* st = dsm + (jt & 1) * ASTAGE;
        const size_t koff = (size_t)((jt * 64 + ii) * BS + b) * (2 * DIMM) + h * HD + cb;
        const char* gKh = (const char*)(KVh + koff);
        const char* gKl = (const char*)(KVl + koff);
        const char* gVh = (const char*)(KVh + koff + DIMM);
        const char* gVl = (const char*)(KVl + koff + DIMM);
        const uint32_t d = smem_u32(st) + ii * 144 + (tid & 1) * 64;
        #pragma unroll
        for (int c = 0; c < 4; c++) {
            CPA(d +         c * 16, gKh + c * 16);
            CPA(d + 9216  + c * 16, gKl + c * 16);
            CPA(d + 18432 + c * 16, gVh + c * 16);
            CPA(d + 27648 + c * 16, gVl + c * 16);
        }
        CPC();
    };

    issue_kv(0);
    {
        const size_t qoff = (size_t)((i0 + ii) * BS + b) * DIMM + h * HD + cb;
        #pragma unroll
        for (int q = 0; q < 4; q++) {
            *(uint4*)&Qh_s[ii][cb + q * 8] = *(const uint4*)&Quh[qoff + q * 8];
            *(uint4*)&Ql_s[ii][cb + q * 8] = *(const uint4*)&Qul[qoff + q * 8];
        }
    }
    __syncthreads();

    uint32_t qh[4][4], ql[4][4];
    #pragma unroll
    for (int s = 0; s < 4; s++) {
        int rowi = w * 16 + (lane & 15);
        int kc  = s * 16 + ((lane & 16) >> 1);
        ldsm4(qh[s], smem_u32(&Qh_s[rowi][kc]));
        ldsm4(ql[s], smem_u32(&Ql_s[rowi][kc]));
    }

    float oacc[8][4] = {};
    float m0 = -1e30f, m1 = -1e30f, l0 = 0.f, l1 = 0.f;

    const int irow0 = i0 + w * 16 + r;
    const float* c2row0 = C2 + ((size_t)bh * CUR + irow0) * FULL;
    const float* c2row1 = c2row0 + (size_t)8 * FULL;

    for (int jt = 0; jt < jtiles; jt++) {
        const int j0 = jt * 64;
        CPW(0);
        __syncthreads();
        if (jt + 1 < jtiles) issue_kv(jt + 1);

        char* st = dsm + (jt & 1) * ASTAGE;
        bf* Kh_s = (bf*)st;
        bf* Kl_s = (bf*)(st + 9216);
        bf* Vh_s = (bf*)(st + 18432);
        bf* Vl_s = (bf*)(st + 27648);

        float sacc[8][4] = {};
        #pragma unroll
        for (int s = 0; s < 4; s++) {
            const int ks = s * 16;
            uint32_t bhf[8][2], blf[8][2];
            #pragma unroll
            for (int g4 = 0; g4 < 4; g4++) {
                int nrow = g4 * 16 + (lane & 15);
                int kc   = ks + ((lane & 16) >> 1);
                uint32_t t[4];
                ldsm4(t, smem_u32(&Kh_s[nrow * 72 + kc]));
                bhf[2*g4][0] = t[0]; bhf[2*g4+1][0] = t[1];
                bhf[2*g4][1] = t[2]; bhf[2*g4+1][1] = t[3];
                ldsm4(t, smem_u32(&Kl_s[nrow * 72 + kc]));
                blf[2*g4][0] = t[0]; blf[2*g4+1][0] = t[1];
                blf[2*g4][1] = t[2]; blf[2*g4+1][1] = t[3];
            }
            #pragma unroll
            for (int g = 0; g < 8; g++) {
                mmabf(sacc[g], qh[s], bhf[g]);
                mmabf(sacc[g], qh[s], blf[g]);
                mmabf(sacc[g], ql[s], bhf[g]);
            }
        }

        const bool boundary = (j0 == i0 + PREV);
        #pragma unroll
        for (int g = 0; g < 8; g++) {
            int jg  = j0 + g * 8 + 2 * cq;
            int k00 = jg - irow0 + 511;
            int k10 = k00 - 8;
            if (!boundary) {
                sacc[g][0] += c2row0[k00];
                sacc[g][1] += c2row0[k00 + 1];
                sacc[g][2] += c2row1[k10];
                sacc[g][3] += c2row1[k10 + 1];
            } else {
                sacc[g][0] = (k00     <= 1023) ? sacc[g][0] + c2row0[k00]     : -1e30f;
                sacc[g][1] = (k00 + 1 <= 1023) ? sacc[g][1] + c2row0[k00 + 1] : -1e30f;
                sacc[g][2] = (k10     <= 1023) ? sacc[g][2] + c2row1[k10]     : -1e30f;
                sacc[g][3] = (k10 + 1 <= 1023) ? sacc[g][3] + c2row1[k10 + 1] : -1e30f;
            }
        }

        float mx0 = -1e30f, mx1 = -1e30f;
        #pragma unroll
        for (int g = 0; g < 8; g++) {
            mx0 = fmaxf(mx0, fmaxf(sacc[g][0], sacc[g][1]));
            mx1 = fmaxf(mx1, fmaxf(sacc[g][2], sacc[g][3]));
        }
        mx0 = fmaxf(mx0, __shfl_xor_sync(0xffffffffu, mx0, 1));
        mx0 = fmaxf(mx0, __shfl_xor_sync(0xffffffffu, mx0, 2));
        mx1 = fmaxf(mx1, __shfl_xor_sync(0xffffffffu, mx1, 1));
        mx1 = fmaxf(mx1, __shfl_xor_sync(0xffffffffu, mx1, 2));

        float mn0 = fmaxf(m0, mx0), mn1 = fmaxf(m1, mx1);
        float a0 = __expf(m0 - mn0), a1 = __expf(m1 - mn1);
        m0 = mn0; m1 = mn1;
        l0 *= a0; l1 *= a1;
        #pragma unroll
        for (int g = 0; g < 8; g++) {
            oacc[g][0] *= a0; oacc[g][1] *= a0;
            oacc[g][2] *= a1; oacc[g][3] *= a1;
        }

        float p[8][4];
        #pragma unroll
        for (int g = 0; g < 8; g++) {
            p[g][0] = __expf(sacc[g][0] - m0);
            p[g][1] = __expf(sacc[g][1] - m0);
            p[g][2] = __expf(sacc[g][2] - m1);
            p[g][3] = __expf(sacc[g][3] - m1);
            l0 += p[g][0] + p[g][1];
            l1 += p[g][2] + p[g][3];
        }

        #pragma unroll
        for (int t4 = 0; t4 < 4; t4++) {
            uint32_t pah[4], pal[4];
            split2(p[2*t4][0],   p[2*t4][1],   pah[0], pal[0]);
            split2(p[2*t4][2],   p[2*t4][3],   pah[1], pal[1]);
            split2(p[2*t4+1][0], p[2*t4+1][1], pah[2], pal[2]);
            split2(p[2*t4+1][2], p[2*t4+1][3], pah[3], pal[3]);

            uint32_t vhf[8][2], vlf[8][2];
            #pragma unroll
            for (int g4 = 0; g4 < 4; g4++) {
                int krow = t4 * 16 + (lane & 15);
                int ncc  = g4 * 16 + ((lane & 16) >> 1);
                uint32_t t[4];
                ldsm4t(t, smem_u32(&Vh_s[krow * 72 + ncc]));
                vhf[2*g4][0] = t[0]; vhf[2*g4][1] = t[1];
                vhf[2*g4+1][0] = t[2]; vhf[2*g4+1][1] = t[3];
                ldsm4t(t, smem_u32(&Vl_s[krow * 72 + ncc]));
                vlf[2*g4][0] = t[0]; vlf[2*g4][1] = t[1];
                vlf[2*g4+1][0] = t[2]; vlf[2*g4+1][1] = t[3];
            }
            #pragma unroll
            for (int g = 0; g < 8; g++) {
                mmabf(oacc[g], pah, vhf[g]);
                mmabf(oacc[g], pah, vlf[g]);
                mmabf(oacc[g], pal, vhf[g]);
            }
        }
    }

    l0 += __shfl_xor_sync(0xffffffffu, l0, 1);
    l0 += __shfl_xor_sync(0xffffffffu, l0, 2);
    l1 += __shfl_xor_sync(0xffffffffu, l1, 1);
    l1 += __shfl_xor_sync(0xffffffffu, l1, 2);
    const float inv0 = 1.f / l0, inv1 = 1.f / l1;

    const size_t o0 = (size_t)(irow0 * BS + b) * DIMM + h * HD;
    const size_t o1 = (size_t)((irow0 + 8) * BS + b) * DIMM + h * HD;
    #pragma unroll
    for (int g = 0; g < 8; g++) {
        int col = g * 8 + 2 * cq;
        store_split(&AVh[o0 + col], &AVl[o0 + col], oacc[g][0] * inv0, oacc[g][1] * inv0);
        store_split(&AVh[o1 + col], &AVl[o1 + col], oacc[g][2] * inv1, oacc[g][3] * inv1);
    }
}

// ---------------------------------------------------------------------------
// Launch
// ---------------------------------------------------------------------------
extern "C" void kernel_launch(void* const* d_in, const int* in_sizes, int n_in,
                              void* d_out, int out_size)
{
    const float* inputs  = (const float*)d_in[0];
    const float* pos_emb = (const float*)d_in[1];
    const float* full_in = (const float*)d_in[2];
    const float* u       = (const float*)d_in[3];
    const float* v       = (const float*)d_in[4];
    const float* W_kv    = (const float*)d_in[5];
    const float* b_kv    = (const float*)d_in[6];
    const float* W_q     = (const float*)d_in[7];
    const float* b_q     = (const float*)d_in[8];
    const float* W_pos   = (const float*)d_in[9];
    const float* b_pos   = (const float*)d_in[10];
    const float* W_proj  = (const float*)d_in[11];
    const float* b_proj  = (const float*)d_in[12];
    float* out = (float*)d_out;

    bf *FIh, *FIl, *INh, *INl, *PEh, *PEl, *Wkvh, *Wkvl, *Wqh, *Wql,
       *Wph, *Wpl, *Wprh, *Wprl, *KVh, *KVl, *Quh, *Qul, *Qvh, *Qvl,
       *Rh, *Rl, *AVh, *AVl;
    float *C2, *scr;
    cudaGetSymbolAddress((void**)&FIh, g_FIh);   cudaGetSymbolAddress((void**)&FIl, g_FIl);
    cudaGetSymbolAddress((void**)&INh, g_INh);   cudaGetSymbolAddress((void**)&INl, g_INl);
    cudaGetSymbolAddress((void**)&PEh, g_PEh);   cudaGetSymbolAddress((void**)&PEl, g_PEl);
    cudaGetSymbolAddress((void**)&Wkvh, g_Wkvh); cudaGetSymbolAddress((void**)&Wkvl, g_Wkvl);
    cudaGetSymbolAddress((void**)&Wqh, g_Wqh);   cudaGetSymbolAddress((void**)&Wql, g_Wql);
    cudaGetSymbolAddress((void**)&Wph, g_Wph);   cudaGetSymbolAddress((void**)&Wpl, g_Wpl);
    cudaGetSymbolAddress((void**)&Wprh, g_Wprh); cudaGetSymbolAddress((void**)&Wprl, g_Wprl);
    cudaGetSymbolAddress((void**)&KVh, g_KVh);   cudaGetSymbolAddress((void**)&KVl, g_KVl);
    cudaGetSymbolAddress((void**)&Quh, g_Quh);   cudaGetSymbolAddress((void**)&Qul, g_Qul);
    cudaGetSymbolAddress((void**)&Qvh, g_Qvh);   cudaGetSymbolAddress((void**)&Qvl, g_Qvl);
    cudaGetSymbolAddress((void**)&Rh, g_Rh);     cudaGetSymbolAddress((void**)&Rl, g_Rl);
    cudaGetSymbolAddress((void**)&AVh, g_AVh);   cudaGetSymbolAddress((void**)&AVl, g_AVl);
    cudaGetSymbolAddress((void**)&C2, g_C2);
    cudaGetSymbolAddress((void**)&scr, g_scr);

    const int GSM = 4 * GSTAGE;     // 151552
    const int ASM = 2 * ASTAGE;     // 73728
    cudaFuncSetAttribute(gemm_mega, cudaFuncAttributeMaxDynamicSharedMemorySize, GSM);
    cudaFuncSetAttribute(attn_ca,   cudaFuncAttributeMaxDynamicSharedMemorySize, ASM);

    // Launches 1-4: trivial (align ncu -s 5 so launch #6 = gemm_mega)
    dummy_k<<<1, 32>>>(scr);
    dummy_k<<<1, 32>>>(scr);
    dummy_k<<<1, 32>>>(scr);
    dummy_k<<<1, 32>>>(scr);

    // Launch 5: all conversions in one grid
    CT ct;
    ct.s[0] = full_in; ct.h[0] = FIh;  ct.l[0] = FIl;
    ct.s[1] = inputs;  ct.h[1] = INh;  ct.l[1] = INl;
    ct.s[2] = pos_emb; ct.h[2] = PEh;  ct.l[2] = PEl;
    ct.s[3] = W_kv;    ct.h[3] = Wkvh; ct.l[3] = Wkvl;
    ct.s[4] = W_q;     ct.h[4] = Wqh;  ct.l[4] = Wql;
    ct.s[5] = W_pos;   ct.h[5] = Wph;  ct.l[5] = Wpl;
    ct.s[6] = W_proj;  ct.h[6] = Wprh; ct.l[6] = Wprl;
    ct.end[0] = 4096;  ct.end[1] = 6144;  ct.end[2] = 7168;
    ct.end[3] = 9216;  ct.end[4] = 10240; ct.end[5] = 11264; ct.end[6] = 12288;
    cvt_mega<<<12288, 256>>>(ct);

    // Launch 6: mega GEMM {KV, Q(+u/v, x0.125), R}
    GT3 ts;
    ts.t[0] = { FIh, FIl, Wkvh, Wkvl, b_kv, nullptr, nullptr,
                nullptr, KVh, KVl, nullptr, nullptr, 2048, 1024, 16, 1 };
    ts.t[1] = { INh, INl, Wqh, Wql, b_q, u, v,
                nullptr, Quh, Qul, Qvh, Qvl, 1024, 1024, 8, 2 };
    ts.t[2] = { PEh, PEl, Wph, Wpl, b_pos, nullptr, nullptr,
                nullptr, Rh, Rl, nullptr, nullptr, 1024, 1024, 8, 1 };
    ts.end0 = 512; ts.end1 = 640;
    gemm_mega<<<704, 256, GSM>>>(ts);

    // Launch 7: position scores (pre-scaled)
    pos_scores_bb<<<dim3(FULL / 64, CUR / 64, BS * NH), 128>>>(Qvh, Qvl, Rh, Rl, C2);

    // Launch 8: fused attention
    attn_ca<<<dim3(CUR / 64, BS * NH), 128, ASM>>>(Quh, Qul, KVh, KVl, C2, AVh, AVl);

    // Launch 9: out = AV @ W_proj + b_proj (fp32)
    GT3 tp;
    tp.t[0] = { AVh, AVl, Wprh, Wprl, b_proj, nullptr, nullptr,
                out, nullptr, nullptr, nullptr, nullptr, 1024, 1024, 8, 0 };
    tp.t[1] = tp.t[0]; tp.t[2] = tp.t[0];
    tp.end0 = 128; tp.end1 = 128;
    gemm_mega<<<128, 256, GSM>>>(tp);
}